// round 15
// baseline (speedup 1.0000x reference)
#include <cuda_runtime.h>
#include <cuda_bf16.h>
#include <math.h>
#include <stdint.h>

#define T_TOK 2048
#define DD    1024
#define SS    20480
#define KPRUNE 819
#define CTARGET (KPRUNE + 256)
#define MAXC  4096
#define MPAD_Q 2176

typedef __nv_bfloat16 bf16;
typedef __nv_bfloat162 bf162;

// ---------------- scratch (device globals) ----------------
__device__ __align__(16) bf16 g_Lh[T_TOK * DD], g_Lm[T_TOK * DD];
__device__ __align__(16) bf16 g_WBh[(size_t)4096 * DD], g_WBm[(size_t)4096 * DD];
__device__ __align__(16) bf16 g_pfh[MPAD_Q * DD], g_pfm[MPAD_Q * DD];
__device__ __align__(16) bf16 g_s1h[(size_t)SS * DD], g_s1m[(size_t)SS * DD];
__device__ float g_h1[T_TOK * DD];
__device__ float g_h2[T_TOK * DD];
__device__ float g_alpha[T_TOK * DD];
__device__ float g_wtd[T_TOK * DD];
__device__ float g_prefix[(T_TOK + 1) * DD];
__device__ float g_csum[16 * DD];
__device__ float g_PaPb[(size_t)T_TOK * 2048];
__device__ float g_Q[MPAD_Q * DD];
__device__ float g_spart[32][SS];
__device__ float g_s1c[(size_t)MAXC * DD];
__device__ float g_rpart[8][MAXC];
__device__ float g_cexact[MAXC];
__device__ float g_zbias[2048];     // zero-initialized, never written
__device__ int   g_hist[65536];
__device__ int   g_cut[1];
__device__ int   g_ccount[1];
__device__ int   g_cidx[MAXC];

// ---------------- helpers ----------------
__device__ __forceinline__ uint32_t smem_u32(const void* p) {
    uint32_t a;
    asm("{ .reg .u64 t; cvta.to.shared.u64 t, %1; cvt.u32.u64 %0, t; }" : "=r"(a) : "l"(p));
    return a;
}
__device__ __forceinline__ void bf16split2(float x, bf16& h, bf16& m) {
    h = __float2bfloat16_rn(x);
    m = __float2bfloat16_rn(x - __bfloat162float(h));
}

#define LDMX4(r, addr)                                                        \
    asm volatile("ldmatrix.sync.aligned.m8n8.x4.shared.b16 {%0,%1,%2,%3}, [%4];" \
        : "=r"((r)[0]), "=r"((r)[1]), "=r"((r)[2]), "=r"((r)[3]) : "r"(addr))

#define MMA16816(c, a, b0, b1)                                                \
    asm volatile("mma.sync.aligned.m16n8k16.row.col.f32.bf16.bf16.f32 "       \
        "{%0,%1,%2,%3},{%4,%5,%6,%7},{%8,%9},{%0,%1,%2,%3};"                  \
        : "+f"((c)[0]), "+f"((c)[1]), "+f"((c)[2]), "+f"((c)[3])              \
        : "r"((a)[0]), "r"((a)[1]), "r"((a)[2]), "r"((a)[3]), "r"(b0), "r"(b1))

#define CPASYNC16(dst, src)                                                   \
    asm volatile("cp.async.cg.shared.global [%0],[%1],16;" :: "r"(dst), "l"(src) : "memory")

// ---------------- R1 fp32 FFMA sgemm (proven precision) ----------------
template <int RELU>
__global__ __launch_bounds__(256, 2)
void sgemm_kernel(const float* __restrict__ A, const float* __restrict__ B,
                  const float* __restrict__ bias, float* __restrict__ C,
                  int M, int K, int N) {
    __shared__ float As[8][128];
    __shared__ float Bs[8][128];
    const int tid = threadIdx.x;
    const int bm = blockIdx.y * 128;
    const int bn = blockIdx.x * 128;
    const int tx = tid & 15;
    const int ty = tid >> 4;
    const int aRow = tid >> 1;
    const int aCol = (tid & 1) * 4;
    const int bRow = tid >> 5;
    const int bCol = (tid & 31) * 4;

    float acc[8][8];
#pragma unroll
    for (int i = 0; i < 8; i++)
#pragma unroll
        for (int j = 0; j < 8; j++) acc[i][j] = 0.f;

    for (int k0 = 0; k0 < K; k0 += 8) {
        float4 av = make_float4(0.f, 0.f, 0.f, 0.f);
        if (bm + aRow < M)
            av = *(const float4*)&A[(size_t)(bm + aRow) * K + k0 + aCol];
        As[aCol + 0][aRow] = av.x;
        As[aCol + 1][aRow] = av.y;
        As[aCol + 2][aRow] = av.z;
        As[aCol + 3][aRow] = av.w;
        *(float4*)&Bs[bRow][bCol] = *(const float4*)&B[(size_t)(k0 + bRow) * N + bn + bCol];
        __syncthreads();
#pragma unroll
        for (int k = 0; k < 8; k++) {
            float a[8], b[8];
            *(float4*)(a)     = *(float4*)&As[k][ty * 8];
            *(float4*)(a + 4) = *(float4*)&As[k][ty * 8 + 4];
            *(float4*)(b)     = *(float4*)&Bs[k][tx * 8];
            *(float4*)(b + 4) = *(float4*)&Bs[k][tx * 8 + 4];
#pragma unroll
            for (int i = 0; i < 8; i++)
#pragma unroll
                for (int j = 0; j < 8; j++) acc[i][j] += a[i] * b[j];
        }
        __syncthreads();
    }
#pragma unroll
    for (int i = 0; i < 8; i++) {
        int row = bm + ty * 8 + i;
        if (row < M) {
#pragma unroll
            for (int j = 0; j < 8; j++) {
                float v = acc[i][j] + bias[bn + tx * 8 + j];
                if (RELU) v = fmaxf(v, 0.f);
                acc[i][j] = v;
            }
            *(float4*)&C[(size_t)row * N + bn + tx * 8]     = *(float4*)&acc[i][0];
            *(float4*)&C[(size_t)row * N + bn + tx * 8 + 4] = *(float4*)&acc[i][4];
        }
    }
}

// ---------------- prep kernels ----------------
__global__ void split2_kernel(const float* __restrict__ in,
                              bf16* __restrict__ oh, bf16* __restrict__ om, int n2) {
    int i = blockIdx.x * 256 + threadIdx.x;
    if (i >= n2) return;
    float2 v = ((const float2*)in)[i];
    bf16 hx, mx, hy, my;
    bf16split2(v.x, hx, mx);
    bf16split2(v.y, hy, my);
    ((bf162*)oh)[i] = bf162(hx, hy);
    ((bf162*)om)[i] = bf162(mx, my);
}

// out planes [N][K] = split2(in[K][N])
__global__ void transpose_split2_kernel(const float* __restrict__ in,
                                        bf16* __restrict__ oh, bf16* __restrict__ om) {
    __shared__ float t[32][33];
    int bx = blockIdx.x * 32, by = blockIdx.y * 32;
#pragma unroll
    for (int i = 0; i < 32; i += 8)
        t[threadIdx.y + i][threadIdx.x] = in[(size_t)(by + threadIdx.y + i) * DD + bx + threadIdx.x];
    __syncthreads();
#pragma unroll
    for (int i = 0; i < 32; i += 8) {
        float v = t[threadIdx.x][threadIdx.y + i];
        bf16 h, m; bf16split2(v, h, m);
        size_t o = (size_t)(bx + threadIdx.y + i) * DD + by + threadIdx.x;
        oh[o] = h; om[o] = m;
    }
}

// ---------------- approx GEMM: 3-MMA bf16 (hh + hm + mh), persistent tiles ----------------
// C[M x N] = A[M x 1024] @ B[N][1024]^T (+bias). Tile 128x256 per iteration.
// 16 warps (512 thr), warp grid 2(M) x 8(N), warp tile 64x32.
// BK=32 per barrier (2 k-steps), 3-stage cp.async pipeline, 80B row stride.
// Grid-stride over ntiles tiles; tile t -> (bn = (t%nx)*256, bm = (t/nx)*128).
// MODE 0: store fp32 C (+bias). MODE 2: fused g_spart scores (slot = (t%nx)*8+wc).
#define ROWB 80
#define SMA3(st, p) ((st) * 61440 + (p) * 10240)
#define SMB3(st, p) ((st) * 61440 + 20480 + (p) * 20480)
#define MM_SMEM2 184320

template <int MODE>
__global__ __launch_bounds__(512, 1)
void mmT3_kernel(const bf16* __restrict__ A0, const bf16* __restrict__ A1,
                 const bf16* __restrict__ B0, const bf16* __restrict__ B1,
                 const float* __restrict__ bias, float* __restrict__ C, int ldc,
                 const float* __restrict__ Ws3, int nx, int ntiles) {
    extern __shared__ char smem[];
    const uint32_t sb = smem_u32(smem);
    const int tid = threadIdx.x;
    const int lane = tid & 31, wid = tid >> 5;          // 16 warps
    const int lg = lane >> 2, lt = lane & 3;
    const int wr = wid >> 3, wc = wid & 7;              // 2 x 8 warp grid
    const bf16* Ap[2] = { A0, A1 };
    const bf16* Bp[2] = { B0, B1 };

    const uint32_t aLaneRow = (lane & 7) + (lane & 8);
    const uint32_t aLaneCol = ((lane >> 4) & 1) * 16;
    const uint32_t bLaneRow = (lane & 7) + (((lane >> 4) & 1) << 3);
    const uint32_t bLaneCol = ((lane >> 3) & 1) * 16;

    for (int t = blockIdx.x; t < ntiles; t += gridDim.x) {
        const int bxt = t % nx;
        const int bm = (t / nx) * 128, bn = bxt * 256;

        float acc[4][4][4];
#pragma unroll
        for (int mi = 0; mi < 4; mi++)
#pragma unroll
            for (int ni = 0; ni < 4; ni++)
#pragma unroll
                for (int q = 0; q < 4; q++) acc[mi][ni][q] = 0.f;

        auto issue = [&](int st, int k0) {
            {
                const int pair = tid >> 1;              // 0..255: (plane, row)
                const int p = pair >> 7, row = pair & 127;
                const int off = (tid & 1) * 32;
                uint32_t d = sb + SMA3(st, p) + row * ROWB + off;
                const bf16* s = Ap[p] + (size_t)(bm + row) * 1024 + k0 + off / 2;
                CPASYNC16(d, s);
                CPASYNC16(d + 16, s + 8);
            }
            {
                const int p = tid >> 8, row = tid & 255;
                uint32_t d = sb + SMB3(st, p) + row * ROWB;
                const bf16* s = Bp[p] + (size_t)(bn + row) * 1024 + k0;
                CPASYNC16(d, s);
                CPASYNC16(d + 16, s + 8);
                CPASYNC16(d + 32, s + 16);
                CPASYNC16(d + 48, s + 24);
            }
            asm volatile("cp.async.commit_group;" ::: "memory");
        };

        issue(0, 0);
        issue(1, 32);

        for (int c = 0; c < 32; c++) {
            const int cur = c % 3;
            if (c < 31) asm volatile("cp.async.wait_group 1;" ::: "memory");
            else        asm volatile("cp.async.wait_group 0;" ::: "memory");
            __syncthreads();
            if (c + 2 < 32) issue((c + 2) % 3, (c + 2) * 32);

#pragma unroll
            for (int ks = 0; ks < 2; ks++) {
                const uint32_t kso = ks * 32;
                uint32_t aFh[4][4], aFm[4][4];
#pragma unroll
                for (int mi = 0; mi < 4; mi++) {
                    uint32_t r = (wr * 64 + mi * 16 + aLaneRow) * ROWB + aLaneCol + kso;
                    LDMX4(aFh[mi], sb + SMA3(cur, 0) + r);
                    LDMX4(aFm[mi], sb + SMA3(cur, 1) + r);
                }
#pragma unroll
                for (int nj = 0; nj < 2; nj++) {
                    uint32_t bFh[4], bFm[4];
                    uint32_t r = (wc * 32 + nj * 16 + bLaneRow) * ROWB + bLaneCol + kso;
                    LDMX4(bFh, sb + SMB3(cur, 0) + r);
                    LDMX4(bFm, sb + SMB3(cur, 1) + r);
#pragma unroll
                    for (int mi = 0; mi < 4; mi++) {
                        MMA16816(acc[mi][nj * 2],     aFh[mi], bFh[0], bFh[1]);
                        MMA16816(acc[mi][nj * 2 + 1], aFh[mi], bFh[2], bFh[3]);
                    }
#pragma unroll
                    for (int mi = 0; mi < 4; mi++) {
                        MMA16816(acc[mi][nj * 2],     aFh[mi], bFm[0], bFm[1]);
                        MMA16816(acc[mi][nj * 2 + 1], aFh[mi], bFm[2], bFm[3]);
                    }
#pragma unroll
                    for (int mi = 0; mi < 4; mi++) {
                        MMA16816(acc[mi][nj * 2],     aFm[mi], bFh[0], bFh[1]);
                        MMA16816(acc[mi][nj * 2 + 1], aFm[mi], bFh[2], bFh[3]);
                    }
                }
            }
        }

        if (MODE == 2) {
            float rsum[4][2];
#pragma unroll
            for (int mi = 0; mi < 4; mi++) { rsum[mi][0] = 0.f; rsum[mi][1] = 0.f; }
#pragma unroll
            for (int ni = 0; ni < 4; ni++) {
                const int col = bn + wc * 32 + ni * 8 + lt * 2;
                const float b0 = bias[col], b1 = bias[col + 1];
                const float w0 = Ws3[col],  w1 = Ws3[col + 1];
#pragma unroll
                for (int mi = 0; mi < 4; mi++) {
                    rsum[mi][0] += fmaxf(acc[mi][ni][0] + b0, 0.f) * w0
                                 + fmaxf(acc[mi][ni][1] + b1, 0.f) * w1;
                    rsum[mi][1] += fmaxf(acc[mi][ni][2] + b0, 0.f) * w0
                                 + fmaxf(acc[mi][ni][3] + b1, 0.f) * w1;
                }
            }
#pragma unroll
            for (int mi = 0; mi < 4; mi++)
#pragma unroll
                for (int h = 0; h < 2; h++) {
                    float v = rsum[mi][h];
                    v += __shfl_xor_sync(0xFFFFFFFFu, v, 1);
                    v += __shfl_xor_sync(0xFFFFFFFFu, v, 2);
                    rsum[mi][h] = v;
                }
            if (lt == 0) {
                const int slot = bxt * 8 + wc;
#pragma unroll
                for (int mi = 0; mi < 4; mi++) {
                    const int r0 = bm + wr * 64 + mi * 16 + lg;
                    g_spart[slot][r0]     = rsum[mi][0];
                    g_spart[slot][r0 + 8] = rsum[mi][1];
                }
            }
        } else {
#pragma unroll
            for (int mi = 0; mi < 4; mi++) {
                const int r0 = bm + wr * 64 + mi * 16 + lg;
#pragma unroll
                for (int ni = 0; ni < 4; ni++) {
                    const int col = bn + wc * 32 + ni * 8 + lt * 2;
                    const float b0 = bias[col], b1 = bias[col + 1];
                    *(float2*)&C[(size_t)r0 * ldc + col] =
                        make_float2(acc[mi][ni][0] + b0, acc[mi][ni][1] + b1);
                    *(float2*)&C[(size_t)(r0 + 8) * ldc + col] =
                        make_float2(acc[mi][ni][2] + b0, acc[mi][ni][3] + b1);
                }
            }
        }
        __syncthreads();   // stage buffers reused by next tile
    }
}

// ---------------- softmax over feature dim, times embeds ----------------
__global__ void softmax_mul_kernel(const float* __restrict__ alpha,
                                   const float* __restrict__ emb,
                                   float* __restrict__ wtd) {
    const int r = blockIdx.x;
    const int tid = threadIdx.x;
    __shared__ float red[256];
    float4 a = ((const float4*)(alpha + (size_t)r * DD))[tid];
    float m = fmaxf(fmaxf(a.x, a.y), fmaxf(a.z, a.w));
    red[tid] = m;
    __syncthreads();
    for (int s = 128; s > 0; s >>= 1) {
        if (tid < s) red[tid] = fmaxf(red[tid], red[tid + s]);
        __syncthreads();
    }
    const float mx = red[0];
    __syncthreads();
    float4 e;
    e.x = expf(a.x - mx); e.y = expf(a.y - mx);
    e.z = expf(a.z - mx); e.w = expf(a.w - mx);
    red[tid] = e.x + e.y + e.z + e.w;
    __syncthreads();
    for (int s = 128; s > 0; s >>= 1) {
        if (tid < s) red[tid] += red[tid + s];
        __syncthreads();
    }
    const float inv = 1.f / red[0];
    float4 em = ((const float4*)(emb + (size_t)r * DD))[tid];
    float4 o;
    o.x = e.x * inv * em.x; o.y = e.y * inv * em.y;
    o.z = e.z * inv * em.z; o.w = e.w * inv * em.w;
    ((float4*)(wtd + (size_t)r * DD))[tid] = o;
}

// ---------------- column-wise prefix sum ----------------
__global__ void scan_chunks_kernel(const float* __restrict__ wtd, float* __restrict__ csum) {
    const int c = blockIdx.x;
    const int col = blockIdx.y * 128 + threadIdx.x;
    float s = 0.f;
#pragma unroll 8
    for (int r = 0; r < 128; r++) s += wtd[(size_t)(c * 128 + r) * DD + col];
    csum[c * DD + col] = s;
}
__global__ void scan_offsets_kernel(float* __restrict__ csum) {
    const int col = blockIdx.x * 256 + threadIdx.x;
    float run = 0.f;
#pragma unroll
    for (int c = 0; c < 16; c++) {
        float t = csum[c * DD + col];
        csum[c * DD + col] = run;
        run += t;
    }
}
__global__ void scan_write2_kernel(const float* __restrict__ wtd, const float* __restrict__ csum,
                                   float* __restrict__ prefix,
                                   bf16* __restrict__ ph, bf16* __restrict__ pm) {
    const int c = blockIdx.x;
    const int col = blockIdx.y * 128 + threadIdx.x;
    float run = csum[c * DD + col];
    if (c == 0) {
        prefix[col] = 0.f;
        ph[col] = __float2bfloat16_rn(0.f);
        pm[col] = __float2bfloat16_rn(0.f);
    }
#pragma unroll 8
    for (int r = 0; r < 128; r++) {
        run += wtd[(size_t)(c * 128 + r) * DD + col];
        size_t o = (size_t)(c * 128 + r + 1) * DD + col;
        prefix[o] = run;
        bf16 h, m; bf16split2(run, h, m);
        ph[o] = h; pm[o] = m;
    }
}

// ---------------- span assembly: g output + split2 approx s1 ----------------
__global__ void assemble_kernel(const float* __restrict__ L,
                                const int* __restrict__ starts,
                                const int* __restrict__ ends,
                                const float* __restrict__ bs1,
                                float* __restrict__ out_g) {
    const int i = blockIdx.x;
    const int t = threadIdx.x;
    const int s = starts[i];
    const int e = ends[i];
    const float4* L4  = (const float4*)L;
    const float4* pf4 = (const float4*)g_prefix;
    const float4* PP4 = (const float4*)g_PaPb;
    const float4* Q4  = (const float4*)g_Q;

    float4 ls = L4[(size_t)s * 256 + t];
    float4 le = L4[(size_t)e * 256 + t];
    float4 pe = pf4[(size_t)(e + 1) * 256 + t];
    float4 ps = pf4[(size_t)s * 256 + t];
    float4 xa = make_float4(pe.x - ps.x, pe.y - ps.y, pe.z - ps.z, pe.w - ps.w);

    float4* go = (float4*)(out_g + (size_t)i * 3072);
    go[t]       = ls;
    go[256 + t] = le;
    go[512 + t] = xa;

    float4 pa = PP4[(size_t)s * 512 + t];
    float4 pb = PP4[(size_t)e * 512 + 256 + t];
    float4 qe = Q4[(size_t)(e + 1) * 256 + t];
    float4 qs = Q4[(size_t)s * 256 + t];
    float4 bb = ((const float4*)bs1)[t];
    float4 v;
    v.x = fmaxf(pa.x + pb.x + qe.x - qs.x + bb.x, 0.f);
    v.y = fmaxf(pa.y + pb.y + qe.y - qs.y + bb.y, 0.f);
    v.z = fmaxf(pa.z + pb.z + qe.z - qs.z + bb.z, 0.f);
    v.w = fmaxf(pa.w + pb.w + qe.w - qs.w + bb.w, 0.f);
    bf16 h0, m0, h1, m1;
    bf16split2(v.x, h0, m0); bf16split2(v.y, h1, m1);
    ((bf162*)g_s1h)[(size_t)i * 512 + t * 2]     = bf162(h0, h1);
    ((bf162*)g_s1m)[(size_t)i * 512 + t * 2]     = bf162(m0, m1);
    bf16split2(v.z, h0, m0); bf16split2(v.w, h1, m1);
    ((bf162*)g_s1h)[(size_t)i * 512 + t * 2 + 1] = bf162(h0, h1);
    ((bf162*)g_s1m)[(size_t)i * 512 + t * 2 + 1] = bf162(m0, m1);
}

// ---------------- approx score reduction ----------------
__global__ void scores_reduce_kernel(const float* __restrict__ bs3, float* __restrict__ out) {
    const int i = blockIdx.x * 256 + threadIdx.x;
    float s = bs3[0];
#pragma unroll
    for (int k = 0; k < 32; k++) s += g_spart[k][i];
    out[i] = s;
}

// ---------------- candidate selection on approx scores ----------------
__device__ __forceinline__ uint32_t fsort(float f) {
    uint32_t u = __float_as_uint(f);
    return (u & 0x80000000u) ? ~u : (u | 0x80000000u);
}
__global__ void hist_zero_kernel() {
    const int i = blockIdx.x * 256 + threadIdx.x;
    if (i < 65536) g_hist[i] = 0;
    if (i == 0) g_ccount[0] = 0;
}
__global__ void hist_build_kernel(const float* __restrict__ sc) {
    const int i = blockIdx.x * 256 + threadIdx.x;
    atomicAdd(&g_hist[fsort(sc[i]) >> 16], 1);
}
__global__ void hist_cut_kernel() {
    __shared__ int part[1024];
    __shared__ int suf[1024];
    const int t = threadIdx.x;
    int s = 0;
#pragma unroll
    for (int j = 0; j < 64; j++) s += g_hist[t * 64 + j];
    part[t] = s;
    __syncthreads();
    if (t == 0) {
        int run = 0;
        for (int i = 1023; i >= 0; i--) { suf[i] = run; run += part[i]; }
    }
    __syncthreads();
    int cum = suf[t];
    for (int j = 63; j >= 0; j--) {
        int h = g_hist[t * 64 + j];
        int ncum = cum + h;
        if (cum < CTARGET && ncum >= CTARGET) g_cut[0] = t * 64 + j;
        cum = ncum;
    }
}
__global__ void cand_build_kernel(const float* __restrict__ sc) {
    const int i = blockIdx.x * 256 + threadIdx.x;
    if ((int)(fsort(sc[i]) >> 16) >= g_cut[0]) {
        int p = atomicAdd(&g_ccount[0], 1);
        if (p < MAXC) g_cidx[p] = i;
    }
}

// ---------------- rescue layer 1: s1c = relu(g[cidx] @ Ws1 + bs1), 64-row tiles ----------------
__global__ __launch_bounds__(256, 4)
void rescue1_kernel(const float* __restrict__ g_all, const float* __restrict__ Ws1,
                    const float* __restrict__ bs1) {
    __shared__ float As[8][68];
    __shared__ float Bs[8][128];
    const int Nc = min(g_ccount[0], MAXC);
    const int bm = blockIdx.y * 64;
    if (bm >= Nc) return;
    const int bn = blockIdx.x * 128;
    const int tid = threadIdx.x;
    const int tx = tid & 15, ty = tid >> 4;
    const int aRow = tid >> 2, aCol = (tid & 3) * 2;
    const int bRow = tid >> 5, bCol = (tid & 31) * 4;
    const int gi = g_cidx[min(bm + aRow, Nc - 1)];
    const float* Arow = g_all + (size_t)gi * 3072 + aCol;

    float acc[4][8];
#pragma unroll
    for (int i = 0; i < 4; i++)
#pragma unroll
        for (int j = 0; j < 8; j++) acc[i][j] = 0.f;

    for (int k0 = 0; k0 < 3072; k0 += 8) {
        float2 av = *(const float2*)(Arow + k0);
        As[aCol][aRow] = av.x;
        As[aCol + 1][aRow] = av.y;
        *(float4*)&Bs[bRow][bCol] = *(const float4*)&Ws1[(size_t)(k0 + bRow) * 1024 + bn + bCol];
        __syncthreads();
#pragma unroll
        for (int k = 0; k < 8; k++) {
            float a[4], b[8];
#pragma unroll
            for (int i = 0; i < 4; i++) a[i] = As[k][ty * 4 + i];
            *(float4*)(b)     = *(float4*)&Bs[k][tx * 8];
            *(float4*)(b + 4) = *(float4*)&Bs[k][tx * 8 + 4];
#pragma unroll
            for (int i = 0; i < 4; i++)
#pragma unroll
                for (int j = 0; j < 8; j++) acc[i][j] += a[i] * b[j];
        }
        __syncthreads();
    }
#pragma unroll
    for (int i = 0; i < 4; i++) {
        int row = bm + ty * 4 + i;
        if (row < Nc) {
#pragma unroll
            for (int j = 0; j < 8; j++)
                acc[i][j] = fmaxf(acc[i][j] + bs1[bn + tx * 8 + j], 0.f);
            *(float4*)&g_s1c[(size_t)row * 1024 + bn + tx * 8]     = *(float4*)&acc[i][0];
            *(float4*)&g_s1c[(size_t)row * 1024 + bn + tx * 8 + 4] = *(float4*)&acc[i][4];
        }
    }
}

// ---------------- rescue layer 2: partials of Ws3 . relu(s1c @ Ws2 + bs2), 64-row tiles ----------------
__global__ __launch_bounds__(256, 4)
void rescue2_kernel(const float* __restrict__ Ws2, const float* __restrict__ bs2,
                    const float* __restrict__ Ws3) {
    __shared__ float As[8][68];
    __shared__ float Bs[8][128];
    __shared__ float rsm[64][17];
    const int Nc = min(g_ccount[0], MAXC);
    const int bm = blockIdx.y * 64;
    if (bm >= Nc) return;
    const int bn = blockIdx.x * 128;
    const int tid = threadIdx.x;
    const int tx = tid & 15, ty = tid >> 4;
    const int aRow = tid >> 2, aCol = (tid & 3) * 2;
    const int bRow = tid >> 5, bCol = (tid & 31) * 4;
    const float* Arow = g_s1c + (size_t)min(bm + aRow, Nc - 1) * 1024 + aCol;

    float acc[4][8];
#pragma unroll
    for (int i = 0; i < 4; i++)
#pragma unroll
        for (int j = 0; j < 8; j++) acc[i][j] = 0.f;

    for (int k0 = 0; k0 < 1024; k0 += 8) {
        float2 av = *(const float2*)(Arow + k0);
        As[aCol][aRow] = av.x;
        As[aCol + 1][aRow] = av.y;
        *(float4*)&Bs[bRow][bCol] = *(const float4*)&Ws2[(size_t)(k0 + bRow) * 1024 + bn + bCol];
        __syncthreads();
#pragma unroll
        for (int k = 0; k < 8; k++) {
            float a[4], b[8];
#pragma unroll
            for (int i = 0; i < 4; i++) a[i] = As[k][ty * 4 + i];
            *(float4*)(b)     = *(float4*)&Bs[k][tx * 8];
            *(float4*)(b + 4) = *(float4*)&Bs[k][tx * 8 + 4];
#pragma unroll
            for (int i = 0; i < 4; i++)
#pragma unroll
                for (int j = 0; j < 8; j++) acc[i][j] += a[i] * b[j];
        }
        __syncthreads();
    }
#pragma unroll
    for (int i = 0; i < 4; i++) {
        float p = 0.f;
#pragma unroll
        for (int j = 0; j < 8; j++) {
            int col = bn + tx * 8 + j;
            p += fmaxf(acc[i][j] + bs2[col], 0.f) * Ws3[col];
        }
        rsm[ty * 4 + i][tx] = p;
    }
    __syncthreads();
    if (tid < 64) {
        float s = 0.f;
#pragma unroll
        for (int j = 0; j < 16; j++) s += rsm[tid][j];
        g_rpart[blockIdx.x][bm + tid] = s;
    }
}

__global__ void rescue_fin_kernel(const float* __restrict__ bs3, float* __restrict__ out_scores) {
    const int i = blockIdx.x * 256 + threadIdx.x;
    const int Nc = min(g_ccount[0], MAXC);
    if (i >= Nc) return;
    float e = bs3[0];
#pragma unroll
    for (int b = 0; b < 8; b++) e += g_rpart[b][i];
    g_cexact[i] = e;
    out_scores[g_cidx[i]] = e;
}

// ---------------- exact top-k among rescued candidates ----------------
__global__ void cand_rank_kernel(float* __restrict__ out_idx) {
    __shared__ float shs[MAXC];
    __shared__ int shi[MAXC];
    const int Nc = min(g_ccount[0], MAXC);
    for (unsigned j = threadIdx.x; j < (unsigned)Nc; j += 1024) {
        shs[j] = g_cexact[j];
        shi[j] = g_cidx[j];
    }
    __syncthreads();
    for (int ib = 0; ib < Nc; ib += 1024) {
        const int i = ib + (int)threadIdx.x;
        if (i >= Nc) break;
        const float my = shs[i];
        const int myi = shi[i];
        int rank = 0;
        for (int j = 0; j < Nc; j++) {
            float v = shs[j];
            rank += (v > my) || (v == my && shi[j] < myi);
        }
        if (rank < KPRUNE) out_idx[rank] = (float)myi;
    }
}

// ---------------- launch ----------------
static void* sym_addr(const void* symbol) {
    void* p = nullptr;
    cudaGetSymbolAddress(&p, symbol);
    return p;
}

extern "C" void kernel_launch(void* const* d_in, const int* in_sizes, int n_in,
                              void* d_out, int out_size) {
    const float* L    = (const float*)d_in[0];
    const float* emb  = (const float*)d_in[1];
    const float* Wa1  = (const float*)d_in[2];
    const float* ba1  = (const float*)d_in[3];
    const float* Wa2  = (const float*)d_in[4];
    const float* ba2  = (const float*)d_in[5];
    const float* Wa3  = (const float*)d_in[6];
    const float* ba3  = (const float*)d_in[7];
    const float* Ws1  = (const float*)d_in[8];
    const float* bs1  = (const float*)d_in[9];
    const float* Ws2  = (const float*)d_in[10];
    const float* bs2  = (const float*)d_in[11];
    const float* Ws3  = (const float*)d_in[12];
    const float* bs3  = (const float*)d_in[13];
    const int* starts = (const int*)d_in[14];
    const int* ends   = (const int*)d_in[15];

    float* out        = (float*)d_out;
    float* out_scores = out;
    float* out_g      = out + SS;
    float* out_idx    = out + SS + (size_t)SS * 3072;

    bf16* Lh  = (bf16*)sym_addr(g_Lh);  bf16* Lm  = (bf16*)sym_addr(g_Lm);
    bf16* WBh = (bf16*)sym_addr(g_WBh); bf16* WBm = (bf16*)sym_addr(g_WBm);
    bf16* pfh = (bf16*)sym_addr(g_pfh); bf16* pfm = (bf16*)sym_addr(g_pfm);
    bf16* s1h = (bf16*)sym_addr(g_s1h); bf16* s1m = (bf16*)sym_addr(g_s1m);
    float* h1  = (float*)sym_addr(g_h1);
    float* h2  = (float*)sym_addr(g_h2);
    float* alp = (float*)sym_addr(g_alpha);
    float* wtd = (float*)sym_addr(g_wtd);
    float* pfx = (float*)sym_addr(g_prefix);
    float* cs  = (float*)sym_addr(g_csum);
    float* PaPb = (float*)sym_addr(g_PaPb);
    float* Q   = (float*)sym_addr(g_Q);
    float* zbias = (float*)sym_addr(g_zbias);

    cudaFuncSetAttribute(mmT3_kernel<0>, cudaFuncAttributeMaxDynamicSharedMemorySize, MM_SMEM2);
    cudaFuncSetAttribute(mmT3_kernel<2>, cudaFuncAttributeMaxDynamicSharedMemorySize, MM_SMEM2);

    const size_t WSZ = (size_t)DD * DD;

    // fork a capture-branch stream for the prep + PaPb work (independent of FFMA chain)
    cudaStream_t sB;
    cudaEvent_t evFork, evJoin;
    cudaStreamCreateWithFlags(&sB, cudaStreamNonBlocking);
    cudaEventCreateWithFlags(&evFork, cudaEventDisableTiming);
    cudaEventCreateWithFlags(&evJoin, cudaEventDisableTiming);
    cudaEventRecord(evFork, 0);
    cudaStreamWaitEvent(sB, evFork, 0);

    // --- stream B: split L, transpose weights, PaPb (bf16 T3) ---
    split2_kernel<<<T_TOK * DD / 2 / 256, 256, 0, sB>>>(L, Lh, Lm, T_TOK * DD / 2);
    transpose_split2_kernel<<<dim3(32, 32), dim3(32, 8), 0, sB>>>(Ws1, WBh, WBm);
    transpose_split2_kernel<<<dim3(32, 32), dim3(32, 8), 0, sB>>>(Ws1 + WSZ, WBh + WSZ, WBm + WSZ);
    mmT3_kernel<0><<<128, 512, MM_SMEM2, sB>>>(Lh, Lm, WBh, WBm,
                                               zbias, PaPb, 2048, zbias, 8, 128);
    transpose_split2_kernel<<<dim3(32, 32), dim3(32, 8), 0, sB>>>(Ws1 + 2 * WSZ, WBh + 2 * WSZ, WBm + 2 * WSZ);
    transpose_split2_kernel<<<dim3(32, 32), dim3(32, 8), 0, sB>>>(Ws2, WBh + 3 * WSZ, WBm + 3 * WSZ);
    cudaEventRecord(evJoin, sB);

    // --- default stream: fp32 FFMA softmax path (precision-critical) ---
    sgemm_kernel<1><<<dim3(8, 16), 256>>>(L, Wa1, ba1, h1, T_TOK, DD, DD);
    sgemm_kernel<1><<<dim3(8, 16), 256>>>(h1, Wa2, ba2, h2, T_TOK, DD, DD);
    sgemm_kernel<0><<<dim3(8, 16), 256>>>(h2, Wa3, ba3, alp, T_TOK, DD, DD);
    softmax_mul_kernel<<<T_TOK, 256>>>(alp, emb, wtd);
    scan_chunks_kernel<<<dim3(16, 8), 128>>>(wtd, cs);
    scan_offsets_kernel<<<4, 256>>>(cs);
    scan_write2_kernel<<<dim3(16, 8), 128>>>(wtd, cs, pfx, pfh, pfm);

    // join: Q needs WB transposes + scan results
    cudaStreamWaitEvent(0, evJoin, 0);
    mmT3_kernel<0><<<68, 512, MM_SMEM2>>>(pfh, pfm, WBh + 2 * WSZ, WBm + 2 * WSZ,
                                          zbias, Q, 1024, zbias, 4, 68);
    // g output + approx s1 planes
    assemble_kernel<<<SS, 256>>>(L, starts, ends, bs1, out_g);
    // fused second layer + score dot (dominant GEMM) — persistent tiles, no wave tail
    mmT3_kernel<2><<<148, 512, MM_SMEM2>>>(s1h, s1m, WBh + 3 * WSZ, WBm + 3 * WSZ,
                                           bs2, nullptr, 0, Ws3, 4, 640);
    scores_reduce_kernel<<<SS / 256, 256>>>(bs3, out_scores);
    // candidate selection
    hist_zero_kernel<<<256, 256>>>();
    hist_build_kernel<<<SS / 256, 256>>>(out_scores);
    hist_cut_kernel<<<1, 1024>>>();
    cand_build_kernel<<<SS / 256, 256>>>(out_scores);
    // exact fp32 rescue
    rescue1_kernel<<<dim3(8, 64), 256>>>(out_g, Ws1, bs1);
    rescue2_kernel<<<dim3(8, 64), 256>>>(Ws2, bs2, Ws3);
    rescue_fin_kernel<<<MAXC / 256, 256>>>(bs3, out_scores);
    // exact ranks
    cand_rank_kernel<<<1, 1024>>>(out_idx);

    cudaEventDestroy(evFork);
    cudaEventDestroy(evJoin);
    cudaStreamDestroy(sB);
}

// round 16
// speedup vs baseline: 1.1001x; 1.1001x over previous
#include <cuda_runtime.h>
#include <cuda_bf16.h>
#include <math.h>
#include <stdint.h>

#define T_TOK 2048
#define DD    1024
#define SS    20480
#define KPRUNE 819
#define CTARGET (KPRUNE + 256)
#define MAXC  4096
#define MPAD_Q 2176

typedef __nv_bfloat16 bf16;
typedef __nv_bfloat162 bf162;

// ---------------- scratch (device globals) ----------------
__device__ __align__(16) bf16 g_Lh[T_TOK * DD], g_Lm[T_TOK * DD];
__device__ __align__(16) bf16 g_WBh[(size_t)7168 * DD], g_WBm[(size_t)7168 * DD];
__device__ __align__(16) bf16 g_h1h[T_TOK * DD], g_h1m[T_TOK * DD];
__device__ __align__(16) bf16 g_h2h[T_TOK * DD], g_h2m[T_TOK * DD];
__device__ __align__(16) bf16 g_pfh[MPAD_Q * DD], g_pfm[MPAD_Q * DD];
__device__ __align__(16) bf16 g_s1h[(size_t)SS * DD], g_s1m[(size_t)SS * DD];
__device__ float g_alpha[T_TOK * DD];
__device__ float g_wtd[T_TOK * DD];
__device__ float g_prefix[(T_TOK + 1) * DD];
__device__ float g_csum[16 * DD];
__device__ float g_PaPb[(size_t)T_TOK * 2048];
__device__ float g_Q[MPAD_Q * DD];
__device__ float g_spart[32][SS];
__device__ float g_s1c[(size_t)MAXC * DD];
__device__ float g_rpart[8][MAXC];
__device__ float g_cexact[MAXC];
__device__ float g_zbias[2048];     // zero-initialized, never written
__device__ int   g_hist[65536];
__device__ int   g_cut[1];
__device__ int   g_ccount[1];
__device__ int   g_cidx[MAXC];

// ---------------- helpers ----------------
__device__ __forceinline__ uint32_t smem_u32(const void* p) {
    uint32_t a;
    asm("{ .reg .u64 t; cvta.to.shared.u64 t, %1; cvt.u32.u64 %0, t; }" : "=r"(a) : "l"(p));
    return a;
}
__device__ __forceinline__ void bf16split2(float x, bf16& h, bf16& m) {
    h = __float2bfloat16_rn(x);
    m = __float2bfloat16_rn(x - __bfloat162float(h));
}

#define LDMX4(r, addr)                                                        \
    asm volatile("ldmatrix.sync.aligned.m8n8.x4.shared.b16 {%0,%1,%2,%3}, [%4];" \
        : "=r"((r)[0]), "=r"((r)[1]), "=r"((r)[2]), "=r"((r)[3]) : "r"(addr))

#define MMA16816(c, a, b0, b1)                                                \
    asm volatile("mma.sync.aligned.m16n8k16.row.col.f32.bf16.bf16.f32 "       \
        "{%0,%1,%2,%3},{%4,%5,%6,%7},{%8,%9},{%0,%1,%2,%3};"                  \
        : "+f"((c)[0]), "+f"((c)[1]), "+f"((c)[2]), "+f"((c)[3])              \
        : "r"((a)[0]), "r"((a)[1]), "r"((a)[2]), "r"((a)[3]), "r"(b0), "r"(b1))

#define CPASYNC16(dst, src)                                                   \
    asm volatile("cp.async.cg.shared.global [%0],[%1],16;" :: "r"(dst), "l"(src) : "memory")

// ---------------- prep kernels ----------------
__global__ void split2_kernel(const float* __restrict__ in,
                              bf16* __restrict__ oh, bf16* __restrict__ om, int n2) {
    int i = blockIdx.x * 256 + threadIdx.x;
    if (i >= n2) return;
    float2 v = ((const float2*)in)[i];
    bf16 hx, mx, hy, my;
    bf16split2(v.x, hx, mx);
    bf16split2(v.y, hy, my);
    ((bf162*)oh)[i] = bf162(hx, hy);
    ((bf162*)om)[i] = bf162(mx, my);
}

// out planes [N][K] = split2(in[K][N])
__global__ void transpose_split2_kernel(const float* __restrict__ in,
                                        bf16* __restrict__ oh, bf16* __restrict__ om) {
    __shared__ float t[32][33];
    int bx = blockIdx.x * 32, by = blockIdx.y * 32;
#pragma unroll
    for (int i = 0; i < 32; i += 8)
        t[threadIdx.y + i][threadIdx.x] = in[(size_t)(by + threadIdx.y + i) * DD + bx + threadIdx.x];
    __syncthreads();
#pragma unroll
    for (int i = 0; i < 32; i += 8) {
        float v = t[threadIdx.x][threadIdx.y + i];
        bf16 h, m; bf16split2(v, h, m);
        size_t o = (size_t)(bx + threadIdx.y + i) * DD + by + threadIdx.x;
        oh[o] = h; om[o] = m;
    }
}

// ---------------- approx GEMM: 3-MMA bf16 (hh + hm + mh), persistent tiles ----------------
// C[M x N] = A[M x 1024] @ B[N][1024]^T (+bias). Tile 128x256 per iteration.
// 16 warps (512 thr), warp grid 2(M) x 8(N), warp tile 64x32.
// BK=32 per barrier (2 k-steps), 3-stage cp.async pipeline, 80B row stride.
// Grid-stride over ntiles; tile t -> (bn = (t%nx)*256, bm = (t/nx)*128).
// MODE 0: store fp32 C (+bias), stride ldc.
// MODE 1: relu(acc+bias) -> split2 -> (Ch, Cm) bf16 planes, stride 1024.
// MODE 2: fused g_spart scores (slot = (t%nx)*8+wc).
#define ROWB 80
#define SMA3(st, p) ((st) * 61440 + (p) * 10240)
#define SMB3(st, p) ((st) * 61440 + 20480 + (p) * 20480)
#define MM_SMEM2 184320

template <int MODE>
__global__ __launch_bounds__(512, 1)
void mmT3_kernel(const bf16* __restrict__ A0, const bf16* __restrict__ A1,
                 const bf16* __restrict__ B0, const bf16* __restrict__ B1,
                 const float* __restrict__ bias, float* __restrict__ C, int ldc,
                 bf16* __restrict__ Ch, bf16* __restrict__ Cm,
                 const float* __restrict__ Ws3, int nx, int ntiles) {
    extern __shared__ char smem[];
    const uint32_t sb = smem_u32(smem);
    const int tid = threadIdx.x;
    const int lane = tid & 31, wid = tid >> 5;          // 16 warps
    const int lg = lane >> 2, lt = lane & 3;
    const int wr = wid >> 3, wc = wid & 7;              // 2 x 8 warp grid
    const bf16* Ap[2] = { A0, A1 };
    const bf16* Bp[2] = { B0, B1 };

    const uint32_t aLaneRow = (lane & 7) + (lane & 8);
    const uint32_t aLaneCol = ((lane >> 4) & 1) * 16;
    const uint32_t bLaneRow = (lane & 7) + (((lane >> 4) & 1) << 3);
    const uint32_t bLaneCol = ((lane >> 3) & 1) * 16;

    for (int t = blockIdx.x; t < ntiles; t += gridDim.x) {
        const int bxt = t % nx;
        const int bm = (t / nx) * 128, bn = bxt * 256;

        float acc[4][4][4];
#pragma unroll
        for (int mi = 0; mi < 4; mi++)
#pragma unroll
            for (int ni = 0; ni < 4; ni++)
#pragma unroll
                for (int q = 0; q < 4; q++) acc[mi][ni][q] = 0.f;

        auto issue = [&](int st, int k0) {
            {
                const int pair = tid >> 1;              // 0..255: (plane, row)
                const int p = pair >> 7, row = pair & 127;
                const int off = (tid & 1) * 32;
                uint32_t d = sb + SMA3(st, p) + row * ROWB + off;
                const bf16* s = Ap[p] + (size_t)(bm + row) * 1024 + k0 + off / 2;
                CPASYNC16(d, s);
                CPASYNC16(d + 16, s + 8);
            }
            {
                const int p = tid >> 8, row = tid & 255;
                uint32_t d = sb + SMB3(st, p) + row * ROWB;
                const bf16* s = Bp[p] + (size_t)(bn + row) * 1024 + k0;
                CPASYNC16(d, s);
                CPASYNC16(d + 16, s + 8);
                CPASYNC16(d + 32, s + 16);
                CPASYNC16(d + 48, s + 24);
            }
            asm volatile("cp.async.commit_group;" ::: "memory");
        };

        issue(0, 0);
        issue(1, 32);

        for (int c = 0; c < 32; c++) {
            const int cur = c % 3;
            if (c < 31) asm volatile("cp.async.wait_group 1;" ::: "memory");
            else        asm volatile("cp.async.wait_group 0;" ::: "memory");
            __syncthreads();
            if (c + 2 < 32) issue((c + 2) % 3, (c + 2) * 32);

#pragma unroll
            for (int ks = 0; ks < 2; ks++) {
                const uint32_t kso = ks * 32;
                uint32_t aFh[4][4], aFm[4][4];
#pragma unroll
                for (int mi = 0; mi < 4; mi++) {
                    uint32_t r = (wr * 64 + mi * 16 + aLaneRow) * ROWB + aLaneCol + kso;
                    LDMX4(aFh[mi], sb + SMA3(cur, 0) + r);
                    LDMX4(aFm[mi], sb + SMA3(cur, 1) + r);
                }
#pragma unroll
                for (int nj = 0; nj < 2; nj++) {
                    uint32_t bFh[4], bFm[4];
                    uint32_t r = (wc * 32 + nj * 16 + bLaneRow) * ROWB + bLaneCol + kso;
                    LDMX4(bFh, sb + SMB3(cur, 0) + r);
                    LDMX4(bFm, sb + SMB3(cur, 1) + r);
#pragma unroll
                    for (int mi = 0; mi < 4; mi++) {
                        MMA16816(acc[mi][nj * 2],     aFh[mi], bFh[0], bFh[1]);
                        MMA16816(acc[mi][nj * 2 + 1], aFh[mi], bFh[2], bFh[3]);
                    }
#pragma unroll
                    for (int mi = 0; mi < 4; mi++) {
                        MMA16816(acc[mi][nj * 2],     aFh[mi], bFm[0], bFm[1]);
                        MMA16816(acc[mi][nj * 2 + 1], aFh[mi], bFm[2], bFm[3]);
                    }
#pragma unroll
                    for (int mi = 0; mi < 4; mi++) {
                        MMA16816(acc[mi][nj * 2],     aFm[mi], bFh[0], bFh[1]);
                        MMA16816(acc[mi][nj * 2 + 1], aFm[mi], bFh[2], bFh[3]);
                    }
                }
            }
        }

        if (MODE == 2) {
            float rsum[4][2];
#pragma unroll
            for (int mi = 0; mi < 4; mi++) { rsum[mi][0] = 0.f; rsum[mi][1] = 0.f; }
#pragma unroll
            for (int ni = 0; ni < 4; ni++) {
                const int col = bn + wc * 32 + ni * 8 + lt * 2;
                const float b0 = bias[col], b1 = bias[col + 1];
                const float w0 = Ws3[col],  w1 = Ws3[col + 1];
#pragma unroll
                for (int mi = 0; mi < 4; mi++) {
                    rsum[mi][0] += fmaxf(acc[mi][ni][0] + b0, 0.f) * w0
                                 + fmaxf(acc[mi][ni][1] + b1, 0.f) * w1;
                    rsum[mi][1] += fmaxf(acc[mi][ni][2] + b0, 0.f) * w0
                                 + fmaxf(acc[mi][ni][3] + b1, 0.f) * w1;
                }
            }
#pragma unroll
            for (int mi = 0; mi < 4; mi++)
#pragma unroll
                for (int h = 0; h < 2; h++) {
                    float v = rsum[mi][h];
                    v += __shfl_xor_sync(0xFFFFFFFFu, v, 1);
                    v += __shfl_xor_sync(0xFFFFFFFFu, v, 2);
                    rsum[mi][h] = v;
                }
            if (lt == 0) {
                const int slot = bxt * 8 + wc;
#pragma unroll
                for (int mi = 0; mi < 4; mi++) {
                    const int r0 = bm + wr * 64 + mi * 16 + lg;
                    g_spart[slot][r0]     = rsum[mi][0];
                    g_spart[slot][r0 + 8] = rsum[mi][1];
                }
            }
        } else if (MODE == 1) {
#pragma unroll
            for (int mi = 0; mi < 4; mi++) {
                const int r0 = bm + wr * 64 + mi * 16 + lg;
#pragma unroll
                for (int ni = 0; ni < 4; ni++) {
                    const int col = bn + wc * 32 + ni * 8 + lt * 2;
                    const float b0 = bias[col], b1 = bias[col + 1];
                    float v0 = fmaxf(acc[mi][ni][0] + b0, 0.f);
                    float v1 = fmaxf(acc[mi][ni][1] + b1, 0.f);
                    float v2 = fmaxf(acc[mi][ni][2] + b0, 0.f);
                    float v3 = fmaxf(acc[mi][ni][3] + b1, 0.f);
                    bf16 h0, m0, h1, m1;
                    bf16split2(v0, h0, m0); bf16split2(v1, h1, m1);
                    *(bf162*)&Ch[(size_t)r0 * 1024 + col] = bf162(h0, h1);
                    *(bf162*)&Cm[(size_t)r0 * 1024 + col] = bf162(m0, m1);
                    bf16split2(v2, h0, m0); bf16split2(v3, h1, m1);
                    *(bf162*)&Ch[(size_t)(r0 + 8) * 1024 + col] = bf162(h0, h1);
                    *(bf162*)&Cm[(size_t)(r0 + 8) * 1024 + col] = bf162(m0, m1);
                }
            }
        } else {
#pragma unroll
            for (int mi = 0; mi < 4; mi++) {
                const int r0 = bm + wr * 64 + mi * 16 + lg;
#pragma unroll
                for (int ni = 0; ni < 4; ni++) {
                    const int col = bn + wc * 32 + ni * 8 + lt * 2;
                    const float b0 = bias[col], b1 = bias[col + 1];
                    *(float2*)&C[(size_t)r0 * ldc + col] =
                        make_float2(acc[mi][ni][0] + b0, acc[mi][ni][1] + b1);
                    *(float2*)&C[(size_t)(r0 + 8) * ldc + col] =
                        make_float2(acc[mi][ni][2] + b0, acc[mi][ni][3] + b1);
                }
            }
        }
        __syncthreads();   // stage buffers reused by next tile
    }
}

// ---------------- softmax over feature dim, times embeds ----------------
__global__ void softmax_mul_kernel(const float* __restrict__ alpha,
                                   const float* __restrict__ emb,
                                   float* __restrict__ wtd) {
    const int r = blockIdx.x;
    const int tid = threadIdx.x;
    __shared__ float red[256];
    float4 a = ((const float4*)(alpha + (size_t)r * DD))[tid];
    float m = fmaxf(fmaxf(a.x, a.y), fmaxf(a.z, a.w));
    red[tid] = m;
    __syncthreads();
    for (int s = 128; s > 0; s >>= 1) {
        if (tid < s) red[tid] = fmaxf(red[tid], red[tid + s]);
        __syncthreads();
    }
    const float mx = red[0];
    __syncthreads();
    float4 e;
    e.x = expf(a.x - mx); e.y = expf(a.y - mx);
    e.z = expf(a.z - mx); e.w = expf(a.w - mx);
    red[tid] = e.x + e.y + e.z + e.w;
    __syncthreads();
    for (int s = 128; s > 0; s >>= 1) {
        if (tid < s) red[tid] += red[tid + s];
        __syncthreads();
    }
    const float inv = 1.f / red[0];
    float4 em = ((const float4*)(emb + (size_t)r * DD))[tid];
    float4 o;
    o.x = e.x * inv * em.x; o.y = e.y * inv * em.y;
    o.z = e.z * inv * em.z; o.w = e.w * inv * em.w;
    ((float4*)(wtd + (size_t)r * DD))[tid] = o;
}

// ---------------- column-wise prefix sum ----------------
__global__ void scan_chunks_kernel(const float* __restrict__ wtd, float* __restrict__ csum) {
    const int c = blockIdx.x;
    const int col = blockIdx.y * 128 + threadIdx.x;
    float s = 0.f;
#pragma unroll 8
    for (int r = 0; r < 128; r++) s += wtd[(size_t)(c * 128 + r) * DD + col];
    csum[c * DD + col] = s;
}
__global__ void scan_offsets_kernel(float* __restrict__ csum) {
    const int col = blockIdx.x * 256 + threadIdx.x;
    float run = 0.f;
#pragma unroll
    for (int c = 0; c < 16; c++) {
        float t = csum[c * DD + col];
        csum[c * DD + col] = run;
        run += t;
    }
}
__global__ void scan_write2_kernel(const float* __restrict__ wtd, const float* __restrict__ csum,
                                   float* __restrict__ prefix,
                                   bf16* __restrict__ ph, bf16* __restrict__ pm) {
    const int c = blockIdx.x;
    const int col = blockIdx.y * 128 + threadIdx.x;
    float run = csum[c * DD + col];
    if (c == 0) {
        prefix[col] = 0.f;
        ph[col] = __float2bfloat16_rn(0.f);
        pm[col] = __float2bfloat16_rn(0.f);
    }
#pragma unroll 8
    for (int r = 0; r < 128; r++) {
        run += wtd[(size_t)(c * 128 + r) * DD + col];
        size_t o = (size_t)(c * 128 + r + 1) * DD + col;
        prefix[o] = run;
        bf16 h, m; bf16split2(run, h, m);
        ph[o] = h; pm[o] = m;
    }
}

// ---------------- span assembly: g output + split2 approx s1 ----------------
__global__ void assemble_kernel(const float* __restrict__ L,
                                const int* __restrict__ starts,
                                const int* __restrict__ ends,
                                const float* __restrict__ bs1,
                                float* __restrict__ out_g) {
    const int i = blockIdx.x;
    const int t = threadIdx.x;
    const int s = starts[i];
    const int e = ends[i];
    const float4* L4  = (const float4*)L;
    const float4* pf4 = (const float4*)g_prefix;
    const float4* PP4 = (const float4*)g_PaPb;
    const float4* Q4  = (const float4*)g_Q;

    float4 ls = L4[(size_t)s * 256 + t];
    float4 le = L4[(size_t)e * 256 + t];
    float4 pe = pf4[(size_t)(e + 1) * 256 + t];
    float4 ps = pf4[(size_t)s * 256 + t];
    float4 xa = make_float4(pe.x - ps.x, pe.y - ps.y, pe.z - ps.z, pe.w - ps.w);

    float4* go = (float4*)(out_g + (size_t)i * 3072);
    go[t]       = ls;
    go[256 + t] = le;
    go[512 + t] = xa;

    float4 pa = PP4[(size_t)s * 512 + t];
    float4 pb = PP4[(size_t)e * 512 + 256 + t];
    float4 qe = Q4[(size_t)(e + 1) * 256 + t];
    float4 qs = Q4[(size_t)s * 256 + t];
    float4 bb = ((const float4*)bs1)[t];
    float4 v;
    v.x = fmaxf(pa.x + pb.x + qe.x - qs.x + bb.x, 0.f);
    v.y = fmaxf(pa.y + pb.y + qe.y - qs.y + bb.y, 0.f);
    v.z = fmaxf(pa.z + pb.z + qe.z - qs.z + bb.z, 0.f);
    v.w = fmaxf(pa.w + pb.w + qe.w - qs.w + bb.w, 0.f);
    bf16 h0, m0, h1, m1;
    bf16split2(v.x, h0, m0); bf16split2(v.y, h1, m1);
    ((bf162*)g_s1h)[(size_t)i * 512 + t * 2]     = bf162(h0, h1);
    ((bf162*)g_s1m)[(size_t)i * 512 + t * 2]     = bf162(m0, m1);
    bf16split2(v.z, h0, m0); bf16split2(v.w, h1, m1);
    ((bf162*)g_s1h)[(size_t)i * 512 + t * 2 + 1] = bf162(h0, h1);
    ((bf162*)g_s1m)[(size_t)i * 512 + t * 2 + 1] = bf162(m0, m1);
}

// ---------------- approx score reduction ----------------
__global__ void scores_reduce_kernel(const float* __restrict__ bs3, float* __restrict__ out) {
    const int i = blockIdx.x * 256 + threadIdx.x;
    float s = bs3[0];
#pragma unroll
    for (int k = 0; k < 32; k++) s += g_spart[k][i];
    out[i] = s;
}

// ---------------- candidate selection on approx scores ----------------
__device__ __forceinline__ uint32_t fsort(float f) {
    uint32_t u = __float_as_uint(f);
    return (u & 0x80000000u) ? ~u : (u | 0x80000000u);
}
__global__ void hist_zero_kernel() {
    const int i = blockIdx.x * 256 + threadIdx.x;
    if (i < 65536) g_hist[i] = 0;
    if (i == 0) g_ccount[0] = 0;
}
__global__ void hist_build_kernel(const float* __restrict__ sc) {
    const int i = blockIdx.x * 256 + threadIdx.x;
    atomicAdd(&g_hist[fsort(sc[i]) >> 16], 1);
}
__global__ void hist_cut_kernel() {
    __shared__ int part[1024];
    __shared__ int suf[1024];
    const int t = threadIdx.x;
    int s = 0;
#pragma unroll
    for (int j = 0; j < 64; j++) s += g_hist[t * 64 + j];
    part[t] = s;
    __syncthreads();
    if (t == 0) {
        int run = 0;
        for (int i = 1023; i >= 0; i--) { suf[i] = run; run += part[i]; }
    }
    __syncthreads();
    int cum = suf[t];
    for (int j = 63; j >= 0; j--) {
        int h = g_hist[t * 64 + j];
        int ncum = cum + h;
        if (cum < CTARGET && ncum >= CTARGET) g_cut[0] = t * 64 + j;
        cum = ncum;
    }
}
__global__ void cand_build_kernel(const float* __restrict__ sc) {
    const int i = blockIdx.x * 256 + threadIdx.x;
    if ((int)(fsort(sc[i]) >> 16) >= g_cut[0]) {
        int p = atomicAdd(&g_ccount[0], 1);
        if (p < MAXC) g_cidx[p] = i;
    }
}

// ---------------- rescue layer 1: s1c = relu(g[cidx] @ Ws1 + bs1), 64-row tiles ----------------
__global__ __launch_bounds__(256, 4)
void rescue1_kernel(const float* __restrict__ g_all, const float* __restrict__ Ws1,
                    const float* __restrict__ bs1) {
    __shared__ float As[8][68];
    __shared__ float Bs[8][128];
    const int Nc = min(g_ccount[0], MAXC);
    const int bm = blockIdx.y * 64;
    if (bm >= Nc) return;
    const int bn = blockIdx.x * 128;
    const int tid = threadIdx.x;
    const int tx = tid & 15, ty = tid >> 4;
    const int aRow = tid >> 2, aCol = (tid & 3) * 2;
    const int bRow = tid >> 5, bCol = (tid & 31) * 4;
    const int gi = g_cidx[min(bm + aRow, Nc - 1)];
    const float* Arow = g_all + (size_t)gi * 3072 + aCol;

    float acc[4][8];
#pragma unroll
    for (int i = 0; i < 4; i++)
#pragma unroll
        for (int j = 0; j < 8; j++) acc[i][j] = 0.f;

    for (int k0 = 0; k0 < 3072; k0 += 8) {
        float2 av = *(const float2*)(Arow + k0);
        As[aCol][aRow] = av.x;
        As[aCol + 1][aRow] = av.y;
        *(float4*)&Bs[bRow][bCol] = *(const float4*)&Ws1[(size_t)(k0 + bRow) * 1024 + bn + bCol];
        __syncthreads();
#pragma unroll
        for (int k = 0; k < 8; k++) {
            float a[4], b[8];
#pragma unroll
            for (int i = 0; i < 4; i++) a[i] = As[k][ty * 4 + i];
            *(float4*)(b)     = *(float4*)&Bs[k][tx * 8];
            *(float4*)(b + 4) = *(float4*)&Bs[k][tx * 8 + 4];
#pragma unroll
            for (int i = 0; i < 4; i++)
#pragma unroll
                for (int j = 0; j < 8; j++) acc[i][j] += a[i] * b[j];
        }
        __syncthreads();
    }
#pragma unroll
    for (int i = 0; i < 4; i++) {
        int row = bm + ty * 4 + i;
        if (row < Nc) {
#pragma unroll
            for (int j = 0; j < 8; j++)
                acc[i][j] = fmaxf(acc[i][j] + bs1[bn + tx * 8 + j], 0.f);
            *(float4*)&g_s1c[(size_t)row * 1024 + bn + tx * 8]     = *(float4*)&acc[i][0];
            *(float4*)&g_s1c[(size_t)row * 1024 + bn + tx * 8 + 4] = *(float4*)&acc[i][4];
        }
    }
}

// ---------------- rescue layer 2: partials of Ws3 . relu(s1c @ Ws2 + bs2), 64-row tiles ----------------
__global__ __launch_bounds__(256, 4)
void rescue2_kernel(const float* __restrict__ Ws2, const float* __restrict__ bs2,
                    const float* __restrict__ Ws3) {
    __shared__ float As[8][68];
    __shared__ float Bs[8][128];
    __shared__ float rsm[64][17];
    const int Nc = min(g_ccount[0], MAXC);
    const int bm = blockIdx.y * 64;
    if (bm >= Nc) return;
    const int bn = blockIdx.x * 128;
    const int tid = threadIdx.x;
    const int tx = tid & 15, ty = tid >> 4;
    const int aRow = tid >> 2, aCol = (tid & 3) * 2;
    const int bRow = tid >> 5, bCol = (tid & 31) * 4;
    const float* Arow = g_s1c + (size_t)min(bm + aRow, Nc - 1) * 1024 + aCol;

    float acc[4][8];
#pragma unroll
    for (int i = 0; i < 4; i++)
#pragma unroll
        for (int j = 0; j < 8; j++) acc[i][j] = 0.f;

    for (int k0 = 0; k0 < 1024; k0 += 8) {
        float2 av = *(const float2*)(Arow + k0);
        As[aCol][aRow] = av.x;
        As[aCol + 1][aRow] = av.y;
        *(float4*)&Bs[bRow][bCol] = *(const float4*)&Ws2[(size_t)(k0 + bRow) * 1024 + bn + bCol];
        __syncthreads();
#pragma unroll
        for (int k = 0; k < 8; k++) {
            float a[4], b[8];
#pragma unroll
            for (int i = 0; i < 4; i++) a[i] = As[k][ty * 4 + i];
            *(float4*)(b)     = *(float4*)&Bs[k][tx * 8];
            *(float4*)(b + 4) = *(float4*)&Bs[k][tx * 8 + 4];
#pragma unroll
            for (int i = 0; i < 4; i++)
#pragma unroll
                for (int j = 0; j < 8; j++) acc[i][j] += a[i] * b[j];
        }
        __syncthreads();
    }
#pragma unroll
    for (int i = 0; i < 4; i++) {
        float p = 0.f;
#pragma unroll
        for (int j = 0; j < 8; j++) {
            int col = bn + tx * 8 + j;
            p += fmaxf(acc[i][j] + bs2[col], 0.f) * Ws3[col];
        }
        rsm[ty * 4 + i][tx] = p;
    }
    __syncthreads();
    if (tid < 64) {
        float s = 0.f;
#pragma unroll
        for (int j = 0; j < 16; j++) s += rsm[tid][j];
        g_rpart[blockIdx.x][bm + tid] = s;
    }
}

__global__ void rescue_fin_kernel(const float* __restrict__ bs3, float* __restrict__ out_scores) {
    const int i = blockIdx.x * 256 + threadIdx.x;
    const int Nc = min(g_ccount[0], MAXC);
    if (i >= Nc) return;
    float e = bs3[0];
#pragma unroll
    for (int b = 0; b < 8; b++) e += g_rpart[b][i];
    g_cexact[i] = e;
    out_scores[g_cidx[i]] = e;
}

// ---------------- exact top-k among rescued candidates ----------------
__global__ void cand_rank_kernel(float* __restrict__ out_idx) {
    __shared__ float shs[MAXC];
    __shared__ int shi[MAXC];
    const int Nc = min(g_ccount[0], MAXC);
    for (unsigned j = threadIdx.x; j < (unsigned)Nc; j += 1024) {
        shs[j] = g_cexact[j];
        shi[j] = g_cidx[j];
    }
    __syncthreads();
    for (int ib = 0; ib < Nc; ib += 1024) {
        const int i = ib + (int)threadIdx.x;
        if (i >= Nc) break;
        const float my = shs[i];
        const int myi = shi[i];
        int rank = 0;
        for (int j = 0; j < Nc; j++) {
            float v = shs[j];
            rank += (v > my) || (v == my && shi[j] < myi);
        }
        if (rank < KPRUNE) out_idx[rank] = (float)myi;
    }
}

// ---------------- launch ----------------
static void* sym_addr(const void* symbol) {
    void* p = nullptr;
    cudaGetSymbolAddress(&p, symbol);
    return p;
}

extern "C" void kernel_launch(void* const* d_in, const int* in_sizes, int n_in,
                              void* d_out, int out_size) {
    const float* L    = (const float*)d_in[0];
    const float* emb  = (const float*)d_in[1];
    const float* Wa1  = (const float*)d_in[2];
    const float* ba1  = (const float*)d_in[3];
    const float* Wa2  = (const float*)d_in[4];
    const float* ba2  = (const float*)d_in[5];
    const float* Wa3  = (const float*)d_in[6];
    const float* ba3  = (const float*)d_in[7];
    const float* Ws1  = (const float*)d_in[8];
    const float* bs1  = (const float*)d_in[9];
    const float* Ws2  = (const float*)d_in[10];
    const float* bs2  = (const float*)d_in[11];
    const float* Ws3  = (const float*)d_in[12];
    const float* bs3  = (const float*)d_in[13];
    const int* starts = (const int*)d_in[14];
    const int* ends   = (const int*)d_in[15];

    float* out        = (float*)d_out;
    float* out_scores = out;
    float* out_g      = out + SS;
    float* out_idx    = out + SS + (size_t)SS * 3072;

    bf16* Lh  = (bf16*)sym_addr(g_Lh);  bf16* Lm  = (bf16*)sym_addr(g_Lm);
    bf16* WBh = (bf16*)sym_addr(g_WBh); bf16* WBm = (bf16*)sym_addr(g_WBm);
    bf16* h1h = (bf16*)sym_addr(g_h1h); bf16* h1m = (bf16*)sym_addr(g_h1m);
    bf16* h2h = (bf16*)sym_addr(g_h2h); bf16* h2m = (bf16*)sym_addr(g_h2m);
    bf16* pfh = (bf16*)sym_addr(g_pfh); bf16* pfm = (bf16*)sym_addr(g_pfm);
    bf16* s1h = (bf16*)sym_addr(g_s1h); bf16* s1m = (bf16*)sym_addr(g_s1m);
    float* alp = (float*)sym_addr(g_alpha);
    float* wtd = (float*)sym_addr(g_wtd);
    float* pfx = (float*)sym_addr(g_prefix);
    float* cs  = (float*)sym_addr(g_csum);
    float* PaPb = (float*)sym_addr(g_PaPb);
    float* Q   = (float*)sym_addr(g_Q);
    float* zbias = (float*)sym_addr(g_zbias);

    cudaFuncSetAttribute(mmT3_kernel<0>, cudaFuncAttributeMaxDynamicSharedMemorySize, MM_SMEM2);
    cudaFuncSetAttribute(mmT3_kernel<1>, cudaFuncAttributeMaxDynamicSharedMemorySize, MM_SMEM2);
    cudaFuncSetAttribute(mmT3_kernel<2>, cudaFuncAttributeMaxDynamicSharedMemorySize, MM_SMEM2);

    const size_t WSZ = (size_t)DD * DD;

    // 1: split L to planes
    split2_kernel<<<T_TOK * DD / 2 / 256, 256>>>(L, Lh, Lm, T_TOK * DD / 2);
    // 2-8: transpose+split weights.
    // Slots: 0=Wa1, 1=Wa2, 2=Wa3, 3=Ws1a, 4=Ws1b (contiguous for fused N=2048), 5=Ws1c, 6=Ws2
    const float* wsrc[7] = { Wa1, Wa2, Wa3, Ws1, Ws1 + WSZ, Ws1 + 2 * WSZ, Ws2 };
    for (int k = 0; k < 7; k++)
        transpose_split2_kernel<<<dim3(32, 32), dim3(32, 8)>>>(
            wsrc[k], WBh + (size_t)k * WSZ, WBm + (size_t)k * WSZ);

    // 9: h1 = relu(L @ Wa1 + ba1) -> planes   [bf16 T3, MODE1]
    mmT3_kernel<1><<<64, 512, MM_SMEM2>>>(Lh, Lm, WBh, WBm,
                                          ba1, nullptr, 0, h1h, h1m, zbias, 4, 64);
    // 10: [Pa|Pb] = L @ [Ws1a|Ws1b]^T   [MODE0]
    mmT3_kernel<0><<<128, 512, MM_SMEM2>>>(Lh, Lm, WBh + 3 * WSZ, WBm + 3 * WSZ,
                                           zbias, PaPb, 2048, nullptr, nullptr, zbias, 8, 128);
    // 11: h2 = relu(h1 @ Wa2 + ba2) -> planes
    mmT3_kernel<1><<<64, 512, MM_SMEM2>>>(h1h, h1m, WBh + 1 * WSZ, WBm + 1 * WSZ,
                                          ba2, nullptr, 0, h2h, h2m, zbias, 4, 64);
    // 12: alpha = h2 @ Wa3 + ba3
    mmT3_kernel<0><<<64, 512, MM_SMEM2>>>(h2h, h2m, WBh + 2 * WSZ, WBm + 2 * WSZ,
                                          ba3, alp, 1024, nullptr, nullptr, zbias, 4, 64);
    // 13: softmax * embeds
    softmax_mul_kernel<<<T_TOK, 256>>>(alp, emb, wtd);
    // 14-16: prefix scan (+ split planes)
    scan_chunks_kernel<<<dim3(16, 8), 128>>>(wtd, cs);
    scan_offsets_kernel<<<4, 256>>>(cs);
    scan_write2_kernel<<<dim3(16, 8), 128>>>(wtd, cs, pfx, pfh, pfm);
    // 17: Q = prefix @ Ws1c^T
    mmT3_kernel<0><<<68, 512, MM_SMEM2>>>(pfh, pfm, WBh + 5 * WSZ, WBm + 5 * WSZ,
                                          zbias, Q, 1024, nullptr, nullptr, zbias, 4, 68);
    // 18: g output + approx s1 planes
    assemble_kernel<<<SS, 256>>>(L, starts, ends, bs1, out_g);
    // 19: fused second layer + score dot (dominant GEMM) — persistent tiles
    mmT3_kernel<2><<<148, 512, MM_SMEM2>>>(s1h, s1m, WBh + 6 * WSZ, WBm + 6 * WSZ,
                                           bs2, nullptr, 0, nullptr, nullptr, Ws3, 4, 640);
    // 20: reduce approx scores
    scores_reduce_kernel<<<SS / 256, 256>>>(bs3, out_scores);
    // 21-24: candidate selection
    hist_zero_kernel<<<256, 256>>>();
    hist_build_kernel<<<SS / 256, 256>>>(out_scores);
    hist_cut_kernel<<<1, 1024>>>();
    cand_build_kernel<<<SS / 256, 256>>>(out_scores);
    // 25-27: exact fp32 rescue
    rescue1_kernel<<<dim3(8, 64), 256>>>(out_g, Ws1, bs1);
    rescue2_kernel<<<dim3(8, 64), 256>>>(Ws2, bs2, Ws3);
    rescue_fin_kernel<<<MAXC / 256, 256>>>(bs3, out_scores);
    // 28: exact ranks
    cand_rank_kernel<<<1, 1024>>>(out_idx);
}

// round 17
// speedup vs baseline: 1.5436x; 1.4032x over previous
#include <cuda_runtime.h>
#include <cuda_bf16.h>
#include <math.h>
#include <stdint.h>

#define T_TOK 2048
#define DD    1024
#define SS    20480
#define KPRUNE 819
#define CTARGET (KPRUNE + 76)
#define MAXC  4096
#define MPAD_Q 2176

typedef __nv_bfloat16 bf16;
typedef __nv_bfloat162 bf162;

// ---------------- scratch (device globals) ----------------
__device__ __align__(16) bf16 g_Lh[T_TOK * DD], g_Lm[T_TOK * DD];
__device__ __align__(16) bf16 g_WBh[(size_t)7168 * DD], g_WBm[(size_t)7168 * DD];
__device__ __align__(16) bf16 g_h1h[T_TOK * DD], g_h1m[T_TOK * DD];
__device__ __align__(16) bf16 g_h2h[T_TOK * DD], g_h2m[T_TOK * DD];
__device__ __align__(16) bf16 g_pfh[MPAD_Q * DD], g_pfm[MPAD_Q * DD];
__device__ __align__(16) bf16 g_s1h[(size_t)SS * DD], g_s1m[(size_t)SS * DD];
__device__ float g_alpha[T_TOK * DD];
__device__ float g_wtd[T_TOK * DD];
__device__ float g_prefix[(T_TOK + 1) * DD];
__device__ float g_csum[16 * DD];
__device__ float g_PaPb[(size_t)T_TOK * 2048];
__device__ float g_Q[MPAD_Q * DD];
__device__ float g_spart[32][SS];
__device__ float g_s1c[(size_t)MAXC * DD];
__device__ float g_r1p[2][(size_t)MAXC * DD];
__device__ float g_rpart[16][MAXC];
__device__ float g_cexact[MAXC];
__device__ float g_zbias[2048];     // zero-initialized, never written
__device__ int   g_hist[65536];
__device__ int   g_cut[1];
__device__ int   g_ccount[1];
__device__ int   g_cidx[MAXC];

// ---------------- helpers ----------------
__device__ __forceinline__ uint32_t smem_u32(const void* p) {
    uint32_t a;
    asm("{ .reg .u64 t; cvta.to.shared.u64 t, %1; cvt.u32.u64 %0, t; }" : "=r"(a) : "l"(p));
    return a;
}
__device__ __forceinline__ void bf16split2(float x, bf16& h, bf16& m) {
    h = __float2bfloat16_rn(x);
    m = __float2bfloat16_rn(x - __bfloat162float(h));
}

#define LDMX4(r, addr)                                                        \
    asm volatile("ldmatrix.sync.aligned.m8n8.x4.shared.b16 {%0,%1,%2,%3}, [%4];" \
        : "=r"((r)[0]), "=r"((r)[1]), "=r"((r)[2]), "=r"((r)[3]) : "r"(addr))

#define MMA16816(c, a, b0, b1)                                                \
    asm volatile("mma.sync.aligned.m16n8k16.row.col.f32.bf16.bf16.f32 "       \
        "{%0,%1,%2,%3},{%4,%5,%6,%7},{%8,%9},{%0,%1,%2,%3};"                  \
        : "+f"((c)[0]), "+f"((c)[1]), "+f"((c)[2]), "+f"((c)[3])              \
        : "r"((a)[0]), "r"((a)[1]), "r"((a)[2]), "r"((a)[3]), "r"(b0), "r"(b1))

#define CPASYNC16(dst, src)                                                   \
    asm volatile("cp.async.cg.shared.global [%0],[%1],16;" :: "r"(dst), "l"(src) : "memory")

// ---------------- prep kernels ----------------
__global__ void split2_kernel(const float* __restrict__ in,
                              bf16* __restrict__ oh, bf16* __restrict__ om, int n2) {
    int i = blockIdx.x * 256 + threadIdx.x;
    if (i >= n2) return;
    float2 v = ((const float2*)in)[i];
    bf16 hx, mx, hy, my;
    bf16split2(v.x, hx, mx);
    bf16split2(v.y, hy, my);
    ((bf162*)oh)[i] = bf162(hx, hy);
    ((bf162*)om)[i] = bf162(mx, my);
}

// out planes [N][K] = split2(in[K][N])
__global__ void transpose_split2_kernel(const float* __restrict__ in,
                                        bf16* __restrict__ oh, bf16* __restrict__ om) {
    __shared__ float t[32][33];
    int bx = blockIdx.x * 32, by = blockIdx.y * 32;
#pragma unroll
    for (int i = 0; i < 32; i += 8)
        t[threadIdx.y + i][threadIdx.x] = in[(size_t)(by + threadIdx.y + i) * DD + bx + threadIdx.x];
    __syncthreads();
#pragma unroll
    for (int i = 0; i < 32; i += 8) {
        float v = t[threadIdx.x][threadIdx.y + i];
        bf16 h, m; bf16split2(v, h, m);
        size_t o = (size_t)(bx + threadIdx.y + i) * DD + by + threadIdx.x;
        oh[o] = h; om[o] = m;
    }
}

// ---------------- approx GEMM: 3-MMA bf16 (hh + hm + mh), persistent tiles ----------------
// C[M x N] = A[M x 1024] @ B[N][1024]^T (+bias). Tile 128 x (128*NJT).
// 16 warps (512 thr), warp grid 2(M) x 8(N), warp tile 64 x (16*NJT).
// BK=32 per barrier, 3-stage cp.async pipeline, 80B row stride.
// Grid-stride over ntiles; tile t -> (bn = (t%nx)*(128*NJT), bm = (t/nx)*128).
// MODE 0: fp32 C (+bias), stride ldc.  MODE 1: relu+split2 -> planes (stride 1024).
// MODE 2 (NJT=2): fused g_spart scores (slot = (t%nx)*8+wc).
#define ROWB 80

template <int MODE, int NJT>
__global__ __launch_bounds__(512, 1)
void mmT3_kernel(const bf16* __restrict__ A0, const bf16* __restrict__ A1,
                 const bf16* __restrict__ B0, const bf16* __restrict__ B1,
                 const float* __restrict__ bias, float* __restrict__ C, int ldc,
                 bf16* __restrict__ Ch, bf16* __restrict__ Cm,
                 const float* __restrict__ Ws3, int nx, int ntiles) {
    constexpr int STAGE = 20480 * (1 + NJT);
    extern __shared__ char smem[];
    const uint32_t sb = smem_u32(smem);
    const int tid = threadIdx.x;
    const int lane = tid & 31, wid = tid >> 5;          // 16 warps
    const int lg = lane >> 2, lt = lane & 3;
    const int wr = wid >> 3, wc = wid & 7;              // 2 x 8 warp grid
    const bf16* Ap[2] = { A0, A1 };
    const bf16* Bp[2] = { B0, B1 };

    const uint32_t aLaneRow = (lane & 7) + (lane & 8);
    const uint32_t aLaneCol = ((lane >> 4) & 1) * 16;
    const uint32_t bLaneRow = (lane & 7) + (((lane >> 4) & 1) << 3);
    const uint32_t bLaneCol = ((lane >> 3) & 1) * 16;

    auto SMA = [&](int st, int p) { return (uint32_t)(st * STAGE + p * 10240); };
    auto SMB = [&](int st, int p) { return (uint32_t)(st * STAGE + 20480 + p * (NJT * 10240)); };

    for (int t = blockIdx.x; t < ntiles; t += gridDim.x) {
        const int bxt = t % nx;
        const int bm = (t / nx) * 128, bn = bxt * (128 * NJT);

        float acc[4][2 * NJT][4];
#pragma unroll
        for (int mi = 0; mi < 4; mi++)
#pragma unroll
            for (int ni = 0; ni < 2 * NJT; ni++)
#pragma unroll
                for (int q = 0; q < 4; q++) acc[mi][ni][q] = 0.f;

        auto issue = [&](int st, int k0) {
            {
                const int pair = tid >> 1;              // (plane, row) for A
                const int p = pair >> 7, row = pair & 127;
                const int off = (tid & 1) * 32;
                uint32_t d = sb + SMA(st, p) + row * ROWB + off;
                const bf16* s = Ap[p] + (size_t)(bm + row) * 1024 + k0 + off / 2;
                CPASYNC16(d, s);
                CPASYNC16(d + 16, s + 8);
            }
            if constexpr (NJT == 2) {
                const int p = tid >> 8, row = tid & 255;
                uint32_t d = sb + SMB(st, p) + row * ROWB;
                const bf16* s = Bp[p] + (size_t)(bn + row) * 1024 + k0;
                CPASYNC16(d, s);
                CPASYNC16(d + 16, s + 8);
                CPASYNC16(d + 32, s + 16);
                CPASYNC16(d + 48, s + 24);
            } else {
                const int pair = tid >> 1;              // (plane, row) for B (128 rows)
                const int p = pair >> 7, row = pair & 127;
                const int off = (tid & 1) * 32;
                uint32_t d = sb + SMB(st, p) + row * ROWB + off;
                const bf16* s = Bp[p] + (size_t)(bn + row) * 1024 + k0 + off / 2;
                CPASYNC16(d, s);
                CPASYNC16(d + 16, s + 8);
            }
            asm volatile("cp.async.commit_group;" ::: "memory");
        };

        issue(0, 0);
        issue(1, 32);

        for (int c = 0; c < 32; c++) {
            const int cur = c % 3;
            if (c < 31) asm volatile("cp.async.wait_group 1;" ::: "memory");
            else        asm volatile("cp.async.wait_group 0;" ::: "memory");
            __syncthreads();
            if (c + 2 < 32) issue((c + 2) % 3, (c + 2) * 32);

#pragma unroll
            for (int ks = 0; ks < 2; ks++) {
                const uint32_t kso = ks * 32;
                uint32_t aFh[4][4], aFm[4][4];
#pragma unroll
                for (int mi = 0; mi < 4; mi++) {
                    uint32_t r = (wr * 64 + mi * 16 + aLaneRow) * ROWB + aLaneCol + kso;
                    LDMX4(aFh[mi], sb + SMA(cur, 0) + r);
                    LDMX4(aFm[mi], sb + SMA(cur, 1) + r);
                }
#pragma unroll
                for (int nj = 0; nj < NJT; nj++) {
                    uint32_t bFh[4], bFm[4];
                    uint32_t r = (wc * (16 * NJT) + nj * 16 + bLaneRow) * ROWB + bLaneCol + kso;
                    LDMX4(bFh, sb + SMB(cur, 0) + r);
                    LDMX4(bFm, sb + SMB(cur, 1) + r);
#pragma unroll
                    for (int mi = 0; mi < 4; mi++) {
                        MMA16816(acc[mi][nj * 2],     aFh[mi], bFh[0], bFh[1]);
                        MMA16816(acc[mi][nj * 2 + 1], aFh[mi], bFh[2], bFh[3]);
                    }
#pragma unroll
                    for (int mi = 0; mi < 4; mi++) {
                        MMA16816(acc[mi][nj * 2],     aFh[mi], bFm[0], bFm[1]);
                        MMA16816(acc[mi][nj * 2 + 1], aFh[mi], bFm[2], bFm[3]);
                    }
#pragma unroll
                    for (int mi = 0; mi < 4; mi++) {
                        MMA16816(acc[mi][nj * 2],     aFm[mi], bFh[0], bFh[1]);
                        MMA16816(acc[mi][nj * 2 + 1], aFm[mi], bFh[2], bFh[3]);
                    }
                }
            }
        }

        if (MODE == 2) {
            float rsum[4][2];
#pragma unroll
            for (int mi = 0; mi < 4; mi++) { rsum[mi][0] = 0.f; rsum[mi][1] = 0.f; }
#pragma unroll
            for (int ni = 0; ni < 2 * NJT; ni++) {
                const int col = bn + wc * (16 * NJT) + ni * 8 + lt * 2;
                const float b0 = bias[col], b1 = bias[col + 1];
                const float w0 = Ws3[col],  w1 = Ws3[col + 1];
#pragma unroll
                for (int mi = 0; mi < 4; mi++) {
                    rsum[mi][0] += fmaxf(acc[mi][ni][0] + b0, 0.f) * w0
                                 + fmaxf(acc[mi][ni][1] + b1, 0.f) * w1;
                    rsum[mi][1] += fmaxf(acc[mi][ni][2] + b0, 0.f) * w0
                                 + fmaxf(acc[mi][ni][3] + b1, 0.f) * w1;
                }
            }
#pragma unroll
            for (int mi = 0; mi < 4; mi++)
#pragma unroll
                for (int h = 0; h < 2; h++) {
                    float v = rsum[mi][h];
                    v += __shfl_xor_sync(0xFFFFFFFFu, v, 1);
                    v += __shfl_xor_sync(0xFFFFFFFFu, v, 2);
                    rsum[mi][h] = v;
                }
            if (lt == 0) {
                const int slot = bxt * 8 + wc;
#pragma unroll
                for (int mi = 0; mi < 4; mi++) {
                    const int r0 = bm + wr * 64 + mi * 16 + lg;
                    g_spart[slot][r0]     = rsum[mi][0];
                    g_spart[slot][r0 + 8] = rsum[mi][1];
                }
            }
        } else if (MODE == 1) {
#pragma unroll
            for (int mi = 0; mi < 4; mi++) {
                const int r0 = bm + wr * 64 + mi * 16 + lg;
#pragma unroll
                for (int ni = 0; ni < 2 * NJT; ni++) {
                    const int col = bn + wc * (16 * NJT) + ni * 8 + lt * 2;
                    const float b0 = bias[col], b1 = bias[col + 1];
                    float v0 = fmaxf(acc[mi][ni][0] + b0, 0.f);
                    float v1 = fmaxf(acc[mi][ni][1] + b1, 0.f);
                    float v2 = fmaxf(acc[mi][ni][2] + b0, 0.f);
                    float v3 = fmaxf(acc[mi][ni][3] + b1, 0.f);
                    bf16 h0, m0, h1, m1;
                    bf16split2(v0, h0, m0); bf16split2(v1, h1, m1);
                    *(bf162*)&Ch[(size_t)r0 * 1024 + col] = bf162(h0, h1);
                    *(bf162*)&Cm[(size_t)r0 * 1024 + col] = bf162(m0, m1);
                    bf16split2(v2, h0, m0); bf16split2(v3, h1, m1);
                    *(bf162*)&Ch[(size_t)(r0 + 8) * 1024 + col] = bf162(h0, h1);
                    *(bf162*)&Cm[(size_t)(r0 + 8) * 1024 + col] = bf162(m0, m1);
                }
            }
        } else {
#pragma unroll
            for (int mi = 0; mi < 4; mi++) {
                const int r0 = bm + wr * 64 + mi * 16 + lg;
#pragma unroll
                for (int ni = 0; ni < 2 * NJT; ni++) {
                    const int col = bn + wc * (16 * NJT) + ni * 8 + lt * 2;
                    const float b0 = bias[col], b1 = bias[col + 1];
                    *(float2*)&C[(size_t)r0 * ldc + col] =
                        make_float2(acc[mi][ni][0] + b0, acc[mi][ni][1] + b1);
                    *(float2*)&C[(size_t)(r0 + 8) * ldc + col] =
                        make_float2(acc[mi][ni][2] + b0, acc[mi][ni][3] + b1);
                }
            }
        }
        __syncthreads();   // stage buffers reused by next tile
    }
}

// ---------------- softmax over feature dim, times embeds ----------------
__global__ void softmax_mul_kernel(const float* __restrict__ alpha,
                                   const float* __restrict__ emb,
                                   float* __restrict__ wtd) {
    const int r = blockIdx.x;
    const int tid = threadIdx.x;
    __shared__ float red[256];
    float4 a = ((const float4*)(alpha + (size_t)r * DD))[tid];
    float m = fmaxf(fmaxf(a.x, a.y), fmaxf(a.z, a.w));
    red[tid] = m;
    __syncthreads();
    for (int s = 128; s > 0; s >>= 1) {
        if (tid < s) red[tid] = fmaxf(red[tid], red[tid + s]);
        __syncthreads();
    }
    const float mx = red[0];
    __syncthreads();
    float4 e;
    e.x = expf(a.x - mx); e.y = expf(a.y - mx);
    e.z = expf(a.z - mx); e.w = expf(a.w - mx);
    red[tid] = e.x + e.y + e.z + e.w;
    __syncthreads();
    for (int s = 128; s > 0; s >>= 1) {
        if (tid < s) red[tid] += red[tid + s];
        __syncthreads();
    }
    const float inv = 1.f / red[0];
    float4 em = ((const float4*)(emb + (size_t)r * DD))[tid];
    float4 o;
    o.x = e.x * inv * em.x; o.y = e.y * inv * em.y;
    o.z = e.z * inv * em.z; o.w = e.w * inv * em.w;
    ((float4*)(wtd + (size_t)r * DD))[tid] = o;
}

// ---------------- column-wise prefix sum ----------------
__global__ void scan_chunks_kernel(const float* __restrict__ wtd, float* __restrict__ csum) {
    const int c = blockIdx.x;
    const int col = blockIdx.y * 128 + threadIdx.x;
    float s = 0.f;
#pragma unroll 8
    for (int r = 0; r < 128; r++) s += wtd[(size_t)(c * 128 + r) * DD + col];
    csum[c * DD + col] = s;
}
__global__ void scan_offsets_kernel(float* __restrict__ csum) {
    const int col = blockIdx.x * 256 + threadIdx.x;
    float run = 0.f;
#pragma unroll
    for (int c = 0; c < 16; c++) {
        float t = csum[c * DD + col];
        csum[c * DD + col] = run;
        run += t;
    }
}
__global__ void scan_write2_kernel(const float* __restrict__ wtd, const float* __restrict__ csum,
                                   float* __restrict__ prefix,
                                   bf16* __restrict__ ph, bf16* __restrict__ pm) {
    const int c = blockIdx.x;
    const int col = blockIdx.y * 128 + threadIdx.x;
    float run = csum[c * DD + col];
    if (c == 0) {
        prefix[col] = 0.f;
        ph[col] = __float2bfloat16_rn(0.f);
        pm[col] = __float2bfloat16_rn(0.f);
    }
#pragma unroll 8
    for (int r = 0; r < 128; r++) {
        run += wtd[(size_t)(c * 128 + r) * DD + col];
        size_t o = (size_t)(c * 128 + r + 1) * DD + col;
        prefix[o] = run;
        bf16 h, m; bf16split2(run, h, m);
        ph[o] = h; pm[o] = m;
    }
}

// ---------------- g write (needs only L + prefix) ----------------
__global__ void g_write_kernel(const float* __restrict__ L,
                               const int* __restrict__ starts,
                               const int* __restrict__ ends,
                               float* __restrict__ out_g) {
    const int i = blockIdx.x;
    const int t = threadIdx.x;
    const int s = starts[i];
    const int e = ends[i];
    const float4* L4  = (const float4*)L;
    const float4* pf4 = (const float4*)g_prefix;

    float4 ls = L4[(size_t)s * 256 + t];
    float4 le = L4[(size_t)e * 256 + t];
    float4 pe = pf4[(size_t)(e + 1) * 256 + t];
    float4 ps = pf4[(size_t)s * 256 + t];
    float4 xa = make_float4(pe.x - ps.x, pe.y - ps.y, pe.z - ps.z, pe.w - ps.w);

    float4* go = (float4*)(out_g + (size_t)i * 3072);
    go[t]       = ls;
    go[256 + t] = le;
    go[512 + t] = xa;
}

// ---------------- approx s1 planes (needs PaPb + Q) ----------------
__global__ void s1_assemble_kernel(const int* __restrict__ starts,
                                   const int* __restrict__ ends,
                                   const float* __restrict__ bs1) {
    const int i = blockIdx.x;
    const int t = threadIdx.x;
    const int s = starts[i];
    const int e = ends[i];
    const float4* PP4 = (const float4*)g_PaPb;
    const float4* Q4  = (const float4*)g_Q;

    float4 pa = PP4[(size_t)s * 512 + t];
    float4 pb = PP4[(size_t)e * 512 + 256 + t];
    float4 qe = Q4[(size_t)(e + 1) * 256 + t];
    float4 qs = Q4[(size_t)s * 256 + t];
    float4 bb = ((const float4*)bs1)[t];
    float4 v;
    v.x = fmaxf(pa.x + pb.x + qe.x - qs.x + bb.x, 0.f);
    v.y = fmaxf(pa.y + pb.y + qe.y - qs.y + bb.y, 0.f);
    v.z = fmaxf(pa.z + pb.z + qe.z - qs.z + bb.z, 0.f);
    v.w = fmaxf(pa.w + pb.w + qe.w - qs.w + bb.w, 0.f);
    bf16 h0, m0, h1, m1;
    bf16split2(v.x, h0, m0); bf16split2(v.y, h1, m1);
    ((bf162*)g_s1h)[(size_t)i * 512 + t * 2]     = bf162(h0, h1);
    ((bf162*)g_s1m)[(size_t)i * 512 + t * 2]     = bf162(m0, m1);
    bf16split2(v.z, h0, m0); bf16split2(v.w, h1, m1);
    ((bf162*)g_s1h)[(size_t)i * 512 + t * 2 + 1] = bf162(h0, h1);
    ((bf162*)g_s1m)[(size_t)i * 512 + t * 2 + 1] = bf162(m0, m1);
}

// ---------------- approx score reduction ----------------
__global__ void scores_reduce_kernel(const float* __restrict__ bs3, float* __restrict__ out) {
    const int i = blockIdx.x * 256 + threadIdx.x;
    float s = bs3[0];
#pragma unroll
    for (int k = 0; k < 32; k++) s += g_spart[k][i];
    out[i] = s;
}

// ---------------- candidate selection on approx scores ----------------
__device__ __forceinline__ uint32_t fsort(float f) {
    uint32_t u = __float_as_uint(f);
    return (u & 0x80000000u) ? ~u : (u | 0x80000000u);
}
__global__ void hist_zero_kernel() {
    const int i = blockIdx.x * 256 + threadIdx.x;
    if (i < 65536) g_hist[i] = 0;
    if (i == 0) g_ccount[0] = 0;
}
__global__ void hist_build_kernel(const float* __restrict__ sc) {
    const int i = blockIdx.x * 256 + threadIdx.x;
    atomicAdd(&g_hist[fsort(sc[i]) >> 16], 1);
}
__global__ void hist_cut_kernel() {
    __shared__ int part[1024];
    __shared__ int suf[1024];
    const int t = threadIdx.x;
    int s = 0;
#pragma unroll
    for (int j = 0; j < 64; j++) s += g_hist[t * 64 + j];
    part[t] = s;
    __syncthreads();
    if (t == 0) {
        int run = 0;
        for (int i = 1023; i >= 0; i--) { suf[i] = run; run += part[i]; }
    }
    __syncthreads();
    int cum = suf[t];
    for (int j = 63; j >= 0; j--) {
        int h = g_hist[t * 64 + j];
        int ncum = cum + h;
        if (cum < CTARGET && ncum >= CTARGET) g_cut[0] = t * 64 + j;
        cum = ncum;
    }
}
__global__ void cand_build_kernel(const float* __restrict__ sc) {
    const int i = blockIdx.x * 256 + threadIdx.x;
    if ((int)(fsort(sc[i]) >> 16) >= g_cut[0]) {
        int p = atomicAdd(&g_ccount[0], 1);
        if (p < MAXC) g_cidx[p] = i;
    }
}

// ---------------- rescue layer 1 (k-split z=2): partials of g[cidx] @ Ws1 ----------------
__global__ __launch_bounds__(256, 4)
void rescue1_kernel(const float* __restrict__ g_all, const float* __restrict__ Ws1) {
    __shared__ float As[8][68];
    __shared__ float Bs[8][128];
    const int Nc = min(g_ccount[0], MAXC);
    const int bm = blockIdx.y * 64;
    if (bm >= Nc) return;
    const int bn = blockIdx.x * 128;
    const int kbase = blockIdx.z * 1536;
    const int tid = threadIdx.x;
    const int tx = tid & 15, ty = tid >> 4;
    const int aRow = tid >> 2, aCol = (tid & 3) * 2;
    const int bRow = tid >> 5, bCol = (tid & 31) * 4;
    const int gi = g_cidx[min(bm + aRow, Nc - 1)];
    const float* Arow = g_all + (size_t)gi * 3072 + kbase + aCol;

    float acc[4][8];
#pragma unroll
    for (int i = 0; i < 4; i++)
#pragma unroll
        for (int j = 0; j < 8; j++) acc[i][j] = 0.f;

    for (int k0 = 0; k0 < 1536; k0 += 8) {
        float2 av = *(const float2*)(Arow + k0);
        As[aCol][aRow] = av.x;
        As[aCol + 1][aRow] = av.y;
        *(float4*)&Bs[bRow][bCol] =
            *(const float4*)&Ws1[(size_t)(kbase + k0 + bRow) * 1024 + bn + bCol];
        __syncthreads();
#pragma unroll
        for (int k = 0; k < 8; k++) {
            float a[4], b[8];
#pragma unroll
            for (int i = 0; i < 4; i++) a[i] = As[k][ty * 4 + i];
            *(float4*)(b)     = *(float4*)&Bs[k][tx * 8];
            *(float4*)(b + 4) = *(float4*)&Bs[k][tx * 8 + 4];
#pragma unroll
            for (int i = 0; i < 4; i++)
#pragma unroll
                for (int j = 0; j < 8; j++) acc[i][j] += a[i] * b[j];
        }
        __syncthreads();
    }
    float* outp = g_r1p[blockIdx.z];
#pragma unroll
    for (int i = 0; i < 4; i++) {
        int row = bm + ty * 4 + i;
        if (row < Nc) {
            *(float4*)&outp[(size_t)row * 1024 + bn + tx * 8]     = *(float4*)&acc[i][0];
            *(float4*)&outp[(size_t)row * 1024 + bn + tx * 8 + 4] = *(float4*)&acc[i][4];
        }
    }
}

// combine: s1c = relu(p0 + p1 + bs1)
__global__ void combine1_kernel(const float* __restrict__ bs1) {
    const int Nc = min(g_ccount[0], MAXC);
    const int i = blockIdx.x * 256 + threadIdx.x;   // float4 index
    if (i >= Nc * 256) return;
    const int col4 = i & 255;
    float4 p0 = ((const float4*)g_r1p[0])[i];
    float4 p1 = ((const float4*)g_r1p[1])[i];
    float4 bb = ((const float4*)bs1)[col4];
    float4 v;
    v.x = fmaxf(p0.x + p1.x + bb.x, 0.f);
    v.y = fmaxf(p0.y + p1.y + bb.y, 0.f);
    v.z = fmaxf(p0.z + p1.z + bb.z, 0.f);
    v.w = fmaxf(p0.w + p1.w + bb.w, 0.f);
    ((float4*)g_s1c)[i] = v;
}

// ---------------- rescue layer 2 (k-split z=2): partials of Ws3 . relu(s1c@Ws2+bs2) ----
__global__ __launch_bounds__(256, 4)
void rescue2_kernel(const float* __restrict__ Ws2, const float* __restrict__ bs2,
                    const float* __restrict__ Ws3) {
    __shared__ float As[8][68];
    __shared__ float Bs[8][128];
    __shared__ float rsm[64][17];
    const int Nc = min(g_ccount[0], MAXC);
    const int bm = blockIdx.y * 64;
    if (bm >= Nc) return;
    const int bn = blockIdx.x * 128;
    const int kbase = blockIdx.z * 512;
    const int tid = threadIdx.x;
    const int tx = tid & 15, ty = tid >> 4;
    const int aRow = tid >> 2, aCol = (tid & 3) * 2;
    const int bRow = tid >> 5, bCol = (tid & 31) * 4;
    const float* Arow = g_s1c + (size_t)min(bm + aRow, Nc - 1) * 1024 + kbase + aCol;

    float acc[4][8];
#pragma unroll
    for (int i = 0; i < 4; i++)
#pragma unroll
        for (int j = 0; j < 8; j++) acc[i][j] = 0.f;

    for (int k0 = 0; k0 < 512; k0 += 8) {
        float2 av = *(const float2*)(Arow + k0);
        As[aCol][aRow] = av.x;
        As[aCol + 1][aRow] = av.y;
        *(float4*)&Bs[bRow][bCol] =
            *(const float4*)&Ws2[(size_t)(kbase + k0 + bRow) * 1024 + bn + bCol];
        __syncthreads();
#pragma unroll
        for (int k = 0; k < 8; k++) {
            float a[4], b[8];
#pragma unroll
            for (int i = 0; i < 4; i++) a[i] = As[k][ty * 4 + i];
            *(float4*)(b)     = *(float4*)&Bs[k][tx * 8];
            *(float4*)(b + 4) = *(float4*)&Bs[k][tx * 8 + 4];
#pragma unroll
            for (int i = 0; i < 4; i++)
#pragma unroll
                for (int j = 0; j < 8; j++) acc[i][j] += a[i] * b[j];
        }
        __syncthreads();
    }
    // NOTE: bias+relu+dot must happen on the FULL s2 value, so partials here are
    // only valid if we defer relu. Instead: z-partials hold raw partial sums; the
    // bias+relu+Ws3 dot is applied in rescue_fin over recombined columns. To keep
    // that cheap we store per-(bx,z) partial DOT is impossible pre-relu, so we
    // store raw column partials to g_r1p (reused) and finish in rescue_fin.
    float* outp = g_r1p[blockIdx.z];   // reuse as [z][row][col] raw partial
#pragma unroll
    for (int i = 0; i < 4; i++) {
        int row = bm + ty * 4 + i;
        if (row < Nc) {
            *(float4*)&outp[(size_t)row * 1024 + bn + tx * 8]     = *(float4*)&acc[i][0];
            *(float4*)&outp[(size_t)row * 1024 + bn + tx * 8 + 4] = *(float4*)&acc[i][4];
        }
    }
    (void)rsm; (void)bs2; (void)Ws3;
}

// finish: e = bs3 + sum_col relu(p0+p1+bs2)*Ws3   (one warp per candidate row)
__global__ void rescue_fin_kernel(const float* __restrict__ bs2,
                                  const float* __restrict__ Ws3,
                                  const float* __restrict__ bs3,
                                  float* __restrict__ out_scores) {
    const int Nc = min(g_ccount[0], MAXC);
    const int warp = (blockIdx.x * 256 + threadIdx.x) >> 5;
    const int lane = threadIdx.x & 31;
    if (warp >= Nc) return;
    const float4* p0 = (const float4*)(g_r1p[0] + (size_t)warp * 1024);
    const float4* p1 = (const float4*)(g_r1p[1] + (size_t)warp * 1024);
    const float4* b4 = (const float4*)bs2;
    const float4* w4 = (const float4*)Ws3;
    float sum = 0.f;
#pragma unroll
    for (int k = lane; k < 256; k += 32) {
        float4 a = p0[k], b = p1[k], bb = b4[k], w = w4[k];
        sum += fmaxf(a.x + b.x + bb.x, 0.f) * w.x
             + fmaxf(a.y + b.y + bb.y, 0.f) * w.y
             + fmaxf(a.z + b.z + bb.z, 0.f) * w.z
             + fmaxf(a.w + b.w + bb.w, 0.f) * w.w;
    }
#pragma unroll
    for (int o = 16; o; o >>= 1) sum += __shfl_xor_sync(0xFFFFFFFFu, sum, o);
    if (lane == 0) {
        float e = sum + bs3[0];
        g_cexact[warp] = e;
        out_scores[g_cidx[warp]] = e;
    }
}

// ---------------- exact top-k among rescued candidates ----------------
__global__ void cand_rank_kernel(float* __restrict__ out_idx) {
    __shared__ float shs[MAXC];
    __shared__ int shi[MAXC];
    const int Nc = min(g_ccount[0], MAXC);
    for (unsigned j = threadIdx.x; j < (unsigned)Nc; j += 1024) {
        shs[j] = g_cexact[j];
        shi[j] = g_cidx[j];
    }
    __syncthreads();
    for (int ib = 0; ib < Nc; ib += 1024) {
        const int i = ib + (int)threadIdx.x;
        if (i >= Nc) break;
        const float my = shs[i];
        const int myi = shi[i];
        int rank = 0;
        for (int j = 0; j < Nc; j++) {
            float v = shs[j];
            rank += (v > my) || (v == my && shi[j] < myi);
        }
        if (rank < KPRUNE) out_idx[rank] = (float)myi;
    }
}

// ---------------- launch ----------------
static void* sym_addr(const void* symbol) {
    void* p = nullptr;
    cudaGetSymbolAddress(&p, symbol);
    return p;
}

extern "C" void kernel_launch(void* const* d_in, const int* in_sizes, int n_in,
                              void* d_out, int out_size) {
    const float* L    = (const float*)d_in[0];
    const float* emb  = (const float*)d_in[1];
    const float* Wa1  = (const float*)d_in[2];
    const float* ba1  = (const float*)d_in[3];
    const float* Wa2  = (const float*)d_in[4];
    const float* ba2  = (const float*)d_in[5];
    const float* Wa3  = (const float*)d_in[6];
    const float* ba3  = (const float*)d_in[7];
    const float* Ws1  = (const float*)d_in[8];
    const float* bs1  = (const float*)d_in[9];
    const float* Ws2  = (const float*)d_in[10];
    const float* bs2  = (const float*)d_in[11];
    const float* Ws3  = (const float*)d_in[12];
    const float* bs3  = (const float*)d_in[13];
    const int* starts = (const int*)d_in[14];
    const int* ends   = (const int*)d_in[15];

    float* out        = (float*)d_out;
    float* out_scores = out;
    float* out_g      = out + SS;
    float* out_idx    = out + SS + (size_t)SS * 3072;

    bf16* Lh  = (bf16*)sym_addr(g_Lh);  bf16* Lm  = (bf16*)sym_addr(g_Lm);
    bf16* WBh = (bf16*)sym_addr(g_WBh); bf16* WBm = (bf16*)sym_addr(g_WBm);
    bf16* h1h = (bf16*)sym_addr(g_h1h); bf16* h1m = (bf16*)sym_addr(g_h1m);
    bf16* h2h = (bf16*)sym_addr(g_h2h); bf16* h2m = (bf16*)sym_addr(g_h2m);
    bf16* pfh = (bf16*)sym_addr(g_pfh); bf16* pfm = (bf16*)sym_addr(g_pfm);
    bf16* s1h = (bf16*)sym_addr(g_s1h); bf16* s1m = (bf16*)sym_addr(g_s1m);
    float* alp = (float*)sym_addr(g_alpha);
    float* wtd = (float*)sym_addr(g_wtd);
    float* pfx = (float*)sym_addr(g_prefix);
    float* cs  = (float*)sym_addr(g_csum);
    float* PaPb = (float*)sym_addr(g_PaPb);
    float* Q   = (float*)sym_addr(g_Q);
    float* zbias = (float*)sym_addr(g_zbias);

    const int SM_NJ2 = 3 * 20480 * 3;   // 184320
    const int SM_NJ1 = 3 * 20480 * 2;   // 122880
    cudaFuncSetAttribute(mmT3_kernel<0, 2>, cudaFuncAttributeMaxDynamicSharedMemorySize, SM_NJ2);
    cudaFuncSetAttribute(mmT3_kernel<2, 2>, cudaFuncAttributeMaxDynamicSharedMemorySize, SM_NJ2);
    cudaFuncSetAttribute(mmT3_kernel<0, 1>, cudaFuncAttributeMaxDynamicSharedMemorySize, SM_NJ1);
    cudaFuncSetAttribute(mmT3_kernel<1, 1>, cudaFuncAttributeMaxDynamicSharedMemorySize, SM_NJ1);

    const size_t WSZ = (size_t)DD * DD;

    cudaStream_t sB;
    cudaEvent_t evFork, evJoin;
    cudaStreamCreateWithFlags(&sB, cudaStreamNonBlocking);
    cudaEventCreateWithFlags(&evFork, cudaEventDisableTiming);
    cudaEventCreateWithFlags(&evJoin, cudaEventDisableTiming);

    // 1: split L to planes
    split2_kernel<<<T_TOK * DD / 2 / 256, 256>>>(L, Lh, Lm, T_TOK * DD / 2);
    // 2-8: transpose+split weights. Slots: 0=Wa1 1=Wa2 2=Wa3 3=Ws1a 4=Ws1b 5=Ws1c 6=Ws2
    const float* wsrc[7] = { Wa1, Wa2, Wa3, Ws1, Ws1 + WSZ, Ws1 + 2 * WSZ, Ws2 };
    for (int k = 0; k < 7; k++)
        transpose_split2_kernel<<<dim3(32, 32), dim3(32, 8)>>>(
            wsrc[k], WBh + (size_t)k * WSZ, WBm + (size_t)k * WSZ);

    // 9: h1 (128-wide tiles, full wave)
    mmT3_kernel<1, 1><<<128, 512, SM_NJ1>>>(Lh, Lm, WBh, WBm,
                                            ba1, nullptr, 0, h1h, h1m, zbias, 8, 128);
    // 10: [Pa|Pb] (256-wide tiles)
    mmT3_kernel<0, 2><<<128, 512, SM_NJ2>>>(Lh, Lm, WBh + 3 * WSZ, WBm + 3 * WSZ,
                                            zbias, PaPb, 2048, nullptr, nullptr, zbias, 8, 128);
    // 11: h2
    mmT3_kernel<1, 1><<<128, 512, SM_NJ1>>>(h1h, h1m, WBh + 1 * WSZ, WBm + 1 * WSZ,
                                            ba2, nullptr, 0, h2h, h2m, zbias, 8, 128);
    // 12: alpha
    mmT3_kernel<0, 1><<<128, 512, SM_NJ1>>>(h2h, h2m, WBh + 2 * WSZ, WBm + 2 * WSZ,
                                            ba3, alp, 1024, nullptr, nullptr, zbias, 8, 128);
    // 13: softmax * embeds
    softmax_mul_kernel<<<T_TOK, 256>>>(alp, emb, wtd);
    // 14-16: prefix scan (+ split planes)
    scan_chunks_kernel<<<dim3(16, 8), 128>>>(wtd, cs);
    scan_offsets_kernel<<<4, 256>>>(cs);
    scan_write2_kernel<<<dim3(16, 8), 128>>>(wtd, cs, pfx, pfh, pfm);

    // fork: Q on stream B, g-write on default (independent)
    cudaEventRecord(evFork, 0);
    cudaStreamWaitEvent(sB, evFork, 0);
    mmT3_kernel<0, 1><<<136, 512, SM_NJ1, sB>>>(pfh, pfm, WBh + 5 * WSZ, WBm + 5 * WSZ,
                                                zbias, Q, 1024, nullptr, nullptr, zbias, 8, 136);
    cudaEventRecord(evJoin, sB);
    g_write_kernel<<<SS, 256>>>(L, starts, ends, out_g);
    cudaStreamWaitEvent(0, evJoin, 0);

    // 18: approx s1 planes
    s1_assemble_kernel<<<SS, 256>>>(starts, ends, bs1);
    // 19: fused second layer + score dot — persistent tiles
    mmT3_kernel<2, 2><<<148, 512, SM_NJ2>>>(s1h, s1m, WBh + 6 * WSZ, WBm + 6 * WSZ,
                                            bs2, nullptr, 0, nullptr, nullptr, Ws3, 4, 640);
    // 20: reduce approx scores
    scores_reduce_kernel<<<SS / 256, 256>>>(bs3, out_scores);
    // 21-24: candidate selection
    hist_zero_kernel<<<256, 256>>>();
    hist_build_kernel<<<SS / 256, 256>>>(out_scores);
    hist_cut_kernel<<<1, 1024>>>();
    cand_build_kernel<<<SS / 256, 256>>>(out_scores);
    // 25-28: exact fp32 rescue (k-split, deterministic partials)
    rescue1_kernel<<<dim3(8, 16, 2), 256>>>(out_g, Ws1);
    combine1_kernel<<<MAXC, 256>>>(bs1);
    rescue2_kernel<<<dim3(8, 16, 2), 256>>>(Ws2, bs2, Ws3);
    rescue_fin_kernel<<<(MAXC * 32 + 255) / 256, 256>>>(bs2, Ws3, bs3, out_scores);
    // 29: exact ranks
    cand_rank_kernel<<<1, 1024>>>(out_idx);

    cudaEventDestroy(evFork);
    cudaEventDestroy(evJoin);
    cudaStreamDestroy(sB);
}